// round 5
// baseline (speedup 1.0000x reference)
#include <cuda_runtime.h>

// Problem constants
#define BATCH 32
#define CDIM  768
#define NTOK  1024
#define NHEAD 12
#define HDIM  64
#define TK    16

// Scratch (device globals — no allocations allowed in kernel_launch)
__device__ float g_w[BATCH * NTOK * CDIM];        // W[b, n, c]   (qkv output)
__device__ float g_ninv[BATCH * NHEAD * HDIM];    // 1 / max(||w||^2 over n, 1e-24)
__device__ float g_pi[BATCH * NHEAD * NTOK];      // Pi[b, h, n]
__device__ float g_attn[BATCH * NHEAD * HDIM];    // attn[b, h, d]

// ---- packed f32x2 helpers (Blackwell FFMA2: 2x fp32 throughput) ----
__device__ __forceinline__ unsigned long long pack2(float x, float y) {
    unsigned long long r;
    asm("mov.b64 %0, {%1, %2};" : "=l"(r) : "f"(x), "f"(y));
    return r;
}
__device__ __forceinline__ float2 unpack2(unsigned long long v) {
    float2 r;
    asm("mov.b64 {%0, %1}, %2;" : "=f"(r.x), "=f"(r.y) : "l"(v));
    return r;
}
#define FFMA2(d, a, b) asm("fma.rn.f32x2 %0, %1, %2, %0;" : "+l"(d) : "l"(a), "l"(b))

// ============================================================================
// GEMM1: W[b,n,o] = sum_c x[b,c,n] * qkv_w[o,c]
// Block tile: 128 n x 128 o, K-step 16. 256 threads, 8x8 outputs/thread
// (cols split as tx*4 and 64+tx*4 for conflict-free smem reads).
// ============================================================================
__global__ __launch_bounds__(256) void gemm1_kernel(
    const float* __restrict__ x, const float* __restrict__ qkv_w)
{
    __shared__ __align__(16) float Xs[TK][132];   // [c][n]
    __shared__ __align__(16) float Qs[TK][132];   // [c][o]
    const int b  = blockIdx.z;
    const int n0 = blockIdx.x * 128;
    const int o0 = blockIdx.y * 128;
    const int tid = threadIdx.x;
    const int tx = tid & 15;          // -> o quad
    const int ty = tid >> 4;          // -> n group of 8
    const int an = (tid & 31) * 4;    // A-load: n offset
    const int ac = tid >> 5;          // A-load: c row (0..7), +8 second pass
    const int bc = (tid & 3) * 4;     // B-load: c offset
    const int bo = tid >> 2;          // B-load: o row (0..63), +64 second pass

    const float* xb = x + (size_t)b * CDIM * NTOK;

    unsigned long long acc[8][4];
#pragma unroll
    for (int i = 0; i < 8; i++)
#pragma unroll
        for (int j = 0; j < 4; j++) acc[i][j] = 0ULL;

    // prologue prefetch (k0 = 0)
    float4 ra0 = *(const float4*)(xb + (size_t)(ac    ) * NTOK + n0 + an);
    float4 ra1 = *(const float4*)(xb + (size_t)(ac + 8) * NTOK + n0 + an);
    float4 rb0 = *(const float4*)(qkv_w + (size_t)(o0 + bo     ) * CDIM + bc);
    float4 rb1 = *(const float4*)(qkv_w + (size_t)(o0 + bo + 64) * CDIM + bc);

    for (int k0 = 0; k0 < CDIM; k0 += TK) {
        // stage prefetched regs into smem
        *(float4*)&Xs[ac][an]     = ra0;
        *(float4*)&Xs[ac + 8][an] = ra1;
        Qs[bc + 0][bo] = rb0.x; Qs[bc + 1][bo] = rb0.y;
        Qs[bc + 2][bo] = rb0.z; Qs[bc + 3][bo] = rb0.w;
        Qs[bc + 0][bo + 64] = rb1.x; Qs[bc + 1][bo + 64] = rb1.y;
        Qs[bc + 2][bo + 64] = rb1.z; Qs[bc + 3][bo + 64] = rb1.w;
        __syncthreads();

        // prefetch next k-tile (overlaps with compute)
        if (k0 + TK < CDIM) {
            int kn = k0 + TK;
            ra0 = *(const float4*)(xb + (size_t)(kn + ac    ) * NTOK + n0 + an);
            ra1 = *(const float4*)(xb + (size_t)(kn + ac + 8) * NTOK + n0 + an);
            rb0 = *(const float4*)(qkv_w + (size_t)(o0 + bo     ) * CDIM + kn + bc);
            rb1 = *(const float4*)(qkv_w + (size_t)(o0 + bo + 64) * CDIM + kn + bc);
        }

#pragma unroll
        for (int kk = 0; kk < TK; kk++) {
            float4 a0 = *(const float4*)&Xs[kk][ty * 8];
            float4 a1 = *(const float4*)&Xs[kk][ty * 8 + 4];
            float4 q0 = *(const float4*)&Qs[kk][tx * 4];
            float4 q1 = *(const float4*)&Qs[kk][64 + tx * 4];
            unsigned long long b2[4] = {
                pack2(q0.x, q0.y), pack2(q0.z, q0.w),
                pack2(q1.x, q1.y), pack2(q1.z, q1.w)
            };
            float a[8] = {a0.x, a0.y, a0.z, a0.w, a1.x, a1.y, a1.z, a1.w};
#pragma unroll
            for (int i = 0; i < 8; i++) {
                unsigned long long ad = pack2(a[i], a[i]);
                FFMA2(acc[i][0], ad, b2[0]);
                FFMA2(acc[i][1], ad, b2[1]);
                FFMA2(acc[i][2], ad, b2[2]);
                FFMA2(acc[i][3], ad, b2[3]);
            }
        }
        __syncthreads();
    }

#pragma unroll
    for (int i = 0; i < 8; i++) {
        float* row = g_w + ((size_t)(b * NTOK + n0 + ty * 8 + i)) * CDIM + o0;
        float2 p0 = unpack2(acc[i][0]);
        float2 p1 = unpack2(acc[i][1]);
        *(float4*)(row + tx * 4) = make_float4(p0.x, p0.y, p1.x, p1.y);
        p0 = unpack2(acc[i][2]);
        p1 = unpack2(acc[i][3]);
        *(float4*)(row + 64 + tx * 4) = make_float4(p0.x, p0.y, p1.x, p1.y);
    }
}

// ============================================================================
// K2: per (b,h,d): ninv = 1 / max( sum_n w^2 , 1e-24 )
// ============================================================================
__global__ __launch_bounds__(256) void norm_kernel()
{
    const int bh = blockIdx.x;             // 0..383
    const int tid = threadIdx.x;
    const int d = tid & 63, g = tid >> 6;
    const int b = bh / NHEAD, h = bh % NHEAD;
    const float* base = g_w + (size_t)b * NTOK * CDIM + h * HDIM + d;
    float acc = 0.f;
    for (int n = g; n < NTOK; n += 4) {
        float v = base[(size_t)n * CDIM];
        acc += v * v;
    }
    __shared__ float red[256];
    red[tid] = acc;
    __syncthreads();
    if (g == 0) {
        float s = red[d] + red[d + 64] + red[d + 128] + red[d + 192];
        g_ninv[bh * HDIM + d] = 1.0f / fmaxf(s, 1e-24f);
    }
}

// ============================================================================
// K3: per (b,n): s[h] = sum_d w^2 * ninv; Pi = softmax over heads of s*temp
// ============================================================================
__global__ __launch_bounds__(256) void pi_kernel(const float* __restrict__ temp)
{
    const int t = blockIdx.x * 256 + threadIdx.x;  // 32768 threads
    const int b = t >> 10, n = t & 1023;
    const float4* wrow = (const float4*)(g_w + ((size_t)b * NTOK + n) * CDIM);
    const float4* nv   = (const float4*)(g_ninv + b * CDIM);

    float sv[NHEAD];
    float m = -1e30f;
#pragma unroll
    for (int h = 0; h < NHEAD; h++) {
        float a = 0.f;
#pragma unroll 4
        for (int q = 0; q < 16; q++) {
            float4 v = wrow[h * 16 + q];
            float4 u = nv[h * 16 + q];
            a += v.x * v.x * u.x + v.y * v.y * u.y
               + v.z * v.z * u.z + v.w * v.w * u.w;
        }
        sv[h] = a * temp[h];
        m = fmaxf(m, sv[h]);
    }
    float e[NHEAD];
    float sum = 0.f;
#pragma unroll
    for (int h = 0; h < NHEAD; h++) { e[h] = expf(sv[h] - m); sum += e[h]; }
    float inv = 1.0f / sum;
#pragma unroll
    for (int h = 0; h < NHEAD; h++)
        g_pi[((b * NHEAD + h) << 10) + n] = e[h] * inv;
}

// ============================================================================
// K4: per (b,h): psum = sum_n Pi; dots[d] = (sum_n Pi*w^2)/(psum+1e-8);
//     attn[d] = 1/(1+dots)
// ============================================================================
__global__ __launch_bounds__(256) void attn_kernel()
{
    const int bh = blockIdx.x;
    const int tid = threadIdx.x;
    const int b = bh / NHEAD, h = bh % NHEAD;
    const float* pi = g_pi + bh * NTOK;

    __shared__ float red[256];
    float pp = 0.f;
    for (int n = tid; n < NTOK; n += 256) pp += pi[n];
    red[tid] = pp;
    __syncthreads();
    for (int s = 128; s > 0; s >>= 1) {
        if (tid < s) red[tid] += red[tid + s];
        __syncthreads();
    }
    float inv = 1.0f / (red[0] + 1e-8f);
    __syncthreads();

    const int d = tid & 63, g = tid >> 6;
    const float* base = g_w + (size_t)b * NTOK * CDIM + h * HDIM + d;
    float acc = 0.f;
    for (int n = g; n < NTOK; n += 4) {
        float v = base[(size_t)n * CDIM];
        acc += pi[n] * v * v;
    }
    red[tid] = acc;
    __syncthreads();
    if (g == 0) {
        float dots = (red[d] + red[d + 64] + red[d + 128] + red[d + 192]) * inv;
        g_attn[bh * HDIM + d] = 1.0f / (1.0f + dots);
    }
}

// ============================================================================
// GEMM2: out[b,o,n] = sum_c ( -W[b,n,c]*Pi[b,h(c),n]*attn[b,h(c),d(c)] ) * out_w[o,c]
//        + out_b[o]      (elementwise transform fused into A-tile load)
// ============================================================================
__global__ __launch_bounds__(256) void gemm2_kernel(
    const float* __restrict__ out_w, const float* __restrict__ out_b,
    float* __restrict__ out)
{
    __shared__ __align__(16) float Ws[TK][132];   // [c][o]
    __shared__ __align__(16) float Ns[TK][132];   // [c][n] (transformed)
    const int b  = blockIdx.z;
    const int n0 = blockIdx.x * 128;
    const int o0 = blockIdx.y * 128;
    const int tid = threadIdx.x;
    const int tx = tid & 15;          // -> n quad
    const int ty = tid >> 4;          // -> o group of 8
    const int wc = (tid & 3) * 4;     // Ws-load c offset
    const int wo = tid >> 2;          // Ws-load o row
    const int nc = (tid & 3) * 4;     // Ns-load c offset
    const int nn = tid >> 2;          // Ns-load n row

    unsigned long long acc[8][4];
#pragma unroll
    for (int i = 0; i < 8; i++)
#pragma unroll
        for (int j = 0; j < 4; j++) acc[i][j] = 0ULL;

    // prologue prefetch (k0 = 0)
    float4 rw0 = *(const float4*)(out_w + (size_t)(o0 + wo     ) * CDIM + wc);
    float4 rw1 = *(const float4*)(out_w + (size_t)(o0 + wo + 64) * CDIM + wc);
    int c = nc, hh = c >> 6, dd = c & 63;
    float4 rat = *(const float4*)(g_attn + (b * NHEAD + hh) * HDIM + dd);
    float4 rv0 = *(const float4*)(g_w + ((size_t)(b * NTOK) + n0 + nn     ) * CDIM + c);
    float4 rv1 = *(const float4*)(g_w + ((size_t)(b * NTOK) + n0 + nn + 64) * CDIM + c);
    float rp0 = g_pi[((b * NHEAD + hh) << 10) + n0 + nn];
    float rp1 = g_pi[((b * NHEAD + hh) << 10) + n0 + nn + 64];

    for (int k0 = 0; k0 < CDIM; k0 += TK) {
        // stage into smem (apply -Pi*attn transform to A)
        Ws[wc + 0][wo] = rw0.x; Ws[wc + 1][wo] = rw0.y;
        Ws[wc + 2][wo] = rw0.z; Ws[wc + 3][wo] = rw0.w;
        Ws[wc + 0][wo + 64] = rw1.x; Ws[wc + 1][wo + 64] = rw1.y;
        Ws[wc + 2][wo + 64] = rw1.z; Ws[wc + 3][wo + 64] = rw1.w;
        {
            float f0 = -rp0, f1 = -rp1;
            Ns[nc + 0][nn] = rv0.x * f0 * rat.x;
            Ns[nc + 1][nn] = rv0.y * f0 * rat.y;
            Ns[nc + 2][nn] = rv0.z * f0 * rat.z;
            Ns[nc + 3][nn] = rv0.w * f0 * rat.w;
            Ns[nc + 0][nn + 64] = rv1.x * f1 * rat.x;
            Ns[nc + 1][nn + 64] = rv1.y * f1 * rat.y;
            Ns[nc + 2][nn + 64] = rv1.z * f1 * rat.z;
            Ns[nc + 3][nn + 64] = rv1.w * f1 * rat.w;
        }
        __syncthreads();

        if (k0 + TK < CDIM) {
            int kn = k0 + TK;
            rw0 = *(const float4*)(out_w + (size_t)(o0 + wo     ) * CDIM + kn + wc);
            rw1 = *(const float4*)(out_w + (size_t)(o0 + wo + 64) * CDIM + kn + wc);
            c = kn + nc; hh = c >> 6; dd = c & 63;
            rat = *(const float4*)(g_attn + (b * NHEAD + hh) * HDIM + dd);
            rv0 = *(const float4*)(g_w + ((size_t)(b * NTOK) + n0 + nn     ) * CDIM + c);
            rv1 = *(const float4*)(g_w + ((size_t)(b * NTOK) + n0 + nn + 64) * CDIM + c);
            rp0 = g_pi[((b * NHEAD + hh) << 10) + n0 + nn];
            rp1 = g_pi[((b * NHEAD + hh) << 10) + n0 + nn + 64];
        }

#pragma unroll
        for (int kk = 0; kk < TK; kk++) {
            float4 a0 = *(const float4*)&Ws[kk][ty * 8];
            float4 a1 = *(const float4*)&Ws[kk][ty * 8 + 4];
            float4 q0 = *(const float4*)&Ns[kk][tx * 4];
            float4 q1 = *(const float4*)&Ns[kk][64 + tx * 4];
            unsigned long long b2[4] = {
                pack2(q0.x, q0.y), pack2(q0.z, q0.w),
                pack2(q1.x, q1.y), pack2(q1.z, q1.w)
            };
            float a[8] = {a0.x, a0.y, a0.z, a0.w, a1.x, a1.y, a1.z, a1.w};
#pragma unroll
            for (int i = 0; i < 8; i++) {
                unsigned long long ad = pack2(a[i], a[i]);
                FFMA2(acc[i][0], ad, b2[0]);
                FFMA2(acc[i][1], ad, b2[1]);
                FFMA2(acc[i][2], ad, b2[2]);
                FFMA2(acc[i][3], ad, b2[3]);
            }
        }
        __syncthreads();
    }

#pragma unroll
    for (int i = 0; i < 8; i++) {
        int o = o0 + ty * 8 + i;
        float bias = out_b[o];
        float* row = out + ((size_t)(b * CDIM) + o) * NTOK + n0;
        float2 p0 = unpack2(acc[i][0]);
        float2 p1 = unpack2(acc[i][1]);
        *(float4*)(row + tx * 4) =
            make_float4(p0.x + bias, p0.y + bias, p1.x + bias, p1.y + bias);
        p0 = unpack2(acc[i][2]);
        p1 = unpack2(acc[i][3]);
        *(float4*)(row + 64 + tx * 4) =
            make_float4(p0.x + bias, p0.y + bias, p1.x + bias, p1.y + bias);
    }
}

// ============================================================================
extern "C" void kernel_launch(void* const* d_in, const int* in_sizes, int n_in,
                              void* d_out, int out_size)
{
    const float* x     = (const float*)d_in[0];   // [32, 768, 32, 32]
    const float* qkv_w = (const float*)d_in[1];   // [768, 768]
    const float* temp  = (const float*)d_in[2];   // [12, 1]
    const float* out_w = (const float*)d_in[3];   // [768, 768]
    const float* out_b = (const float*)d_in[4];   // [768]
    float* out = (float*)d_out;                   // [32, 768, 32, 32]

    dim3 g1(NTOK / 128, CDIM / 128, BATCH);       // 8 x 6 x 32
    gemm1_kernel<<<g1, 256>>>(x, qkv_w);
    norm_kernel<<<BATCH * NHEAD, 256>>>();
    pi_kernel<<<(BATCH * NTOK) / 256, 256>>>(temp);
    attn_kernel<<<BATCH * NHEAD, 256>>>();
    gemm2_kernel<<<g1, 256>>>(out_w, out_b, out);
}

// round 6
// speedup vs baseline: 1.0294x; 1.0294x over previous
#include <cuda_runtime.h>
#include <cuda_bf16.h>

#define BATCH 32
#define CDIM  768
#define NTOK  1024
#define NHEAD 12
#define HDIM  64
#define PITCH 24      // bf16 elems per smem tile row (16 data + 8 pad)
#define KSTEPS (CDIM / 16)

// Scratch (device globals — no allocations allowed)
__device__ float g_w[BATCH * NTOK * CDIM];      // W[b, n, c]
__device__ float g_ninv[BATCH * NHEAD * HDIM];  // 1 / max(||w||^2 over n, 1e-24)
__device__ float g_pi[BATCH * NHEAD * NTOK];    // Pi[b, h, n]
__device__ float g_attn[BATCH * NHEAD * HDIM];  // attn[b, h, d]

// ---------------------------------------------------------------------------
// mma helpers
// ---------------------------------------------------------------------------
__device__ __forceinline__ unsigned smem_u32(const void* p) {
    return (unsigned)__cvta_generic_to_shared(p);
}
__device__ __forceinline__ void ldmatrix_x4(unsigned& r0, unsigned& r1,
                                            unsigned& r2, unsigned& r3, unsigned a) {
    asm volatile("ldmatrix.sync.aligned.m8n8.x4.shared.b16 {%0,%1,%2,%3}, [%4];"
                 : "=r"(r0), "=r"(r1), "=r"(r2), "=r"(r3) : "r"(a));
}
__device__ __forceinline__ void ldmatrix_x2(unsigned& r0, unsigned& r1, unsigned a) {
    asm volatile("ldmatrix.sync.aligned.m8n8.x2.shared.b16 {%0,%1}, [%2];"
                 : "=r"(r0), "=r"(r1) : "r"(a));
}
__device__ __forceinline__ void mma16816(float* c, const unsigned* a, const unsigned* b) {
    asm volatile(
        "mma.sync.aligned.m16n8k16.row.col.f32.bf16.bf16.f32 "
        "{%0,%1,%2,%3}, {%4,%5,%6,%7}, {%8,%9}, {%0,%1,%2,%3};"
        : "+f"(c[0]), "+f"(c[1]), "+f"(c[2]), "+f"(c[3])
        : "r"(a[0]), "r"(a[1]), "r"(a[2]), "r"(a[3]), "r"(b[0]), "r"(b[1]));
}

typedef __nv_bfloat16 (*TileP)[PITCH];

// Fragment-load + 48 mma for one K=16 stage (shared by both GEMMs).
__device__ __forceinline__ void mma_stage(
    float acc[4][4][4], TileP Ah_, TileP Al_, TileP Bh_, TileP Bl_,
    int wm0, int wn0, int lane)
{
    unsigned ah[4][4], al[4][4], bhf[4][2], blf[4][2];
    const int arow = wm0 + (lane & 15);
    const int acol = ((lane >> 4) & 1) * 8;
#pragma unroll
    for (int mi = 0; mi < 4; mi++) {
        ldmatrix_x4(ah[mi][0], ah[mi][1], ah[mi][2], ah[mi][3],
                    smem_u32(&Ah_[arow + mi * 16][acol]));
        ldmatrix_x4(al[mi][0], al[mi][1], al[mi][2], al[mi][3],
                    smem_u32(&Al_[arow + mi * 16][acol]));
    }
    const int brow = wn0 + (lane & 7);
    const int bcol = ((lane >> 3) & 1) * 8;
#pragma unroll
    for (int ni = 0; ni < 4; ni++) {
        ldmatrix_x2(bhf[ni][0], bhf[ni][1], smem_u32(&Bh_[brow + ni * 8][bcol]));
        ldmatrix_x2(blf[ni][0], blf[ni][1], smem_u32(&Bl_[brow + ni * 8][bcol]));
    }
#pragma unroll
    for (int mi = 0; mi < 4; mi++)
#pragma unroll
        for (int ni = 0; ni < 4; ni++) {
            mma16816(acc[mi][ni], ah[mi], bhf[ni]);   // hi*hi
            mma16816(acc[mi][ni], ah[mi], blf[ni]);   // hi*lo
            mma16816(acc[mi][ni], al[mi], bhf[ni]);   // lo*hi
        }
}

// ===========================================================================
// GEMM1: W[b,n,o] = sum_c x[b,c,n] * qkv_w[o,c]
//   M = n (128-tile), N = o (128-tile), K = c. A = x^T (transpose fused into
//   tile load), B = qkv_w (k-contiguous). fp32 -> bf16 hi/lo split on load.
// ===========================================================================
__global__ __launch_bounds__(256) void gemm1_mma(
    const float* __restrict__ x, const float* __restrict__ qkv_w)
{
    __shared__ __nv_bfloat16 Ah[2][128][PITCH];
    __shared__ __nv_bfloat16 Al[2][128][PITCH];
    __shared__ __nv_bfloat16 Bh[2][128][PITCH];
    __shared__ __nv_bfloat16 Bl[2][128][PITCH];

    const int b   = blockIdx.z;
    const int n0  = blockIdx.x * 128;
    const int o0  = blockIdx.y * 128;
    const int tid = threadIdx.x;
    const int lane = tid & 31, wid = tid >> 5;
    const int wm0 = (wid >> 2) * 64;
    const int wn0 = (wid & 3) * 32;

    // tile-load thread mapping
    const int ac = tid >> 4;             // c row within k-tile (0..15)
    const int an = (tid & 15) * 8;       // n col (8 per thread)
    const int bo = tid >> 1;             // o row (0..127)
    const int bk = (tid & 1) * 8;        // k col (0 or 8)

    const float* xA = x + (size_t)b * (CDIM * NTOK) + (size_t)ac * NTOK + n0 + an;
    const float* wB = qkv_w + (size_t)(o0 + bo) * CDIM + bk;

    float acc[4][4][4];
#pragma unroll
    for (int i = 0; i < 4; i++)
#pragma unroll
        for (int j = 0; j < 4; j++)
#pragma unroll
            for (int e = 0; e < 4; e++) acc[i][j][e] = 0.f;

    float ar[8], br[8];
    auto load = [&](int k0) {
        const float4* pa = (const float4*)(xA + (size_t)k0 * NTOK);
        float4 v0 = pa[0], v1 = pa[1];
        ar[0] = v0.x; ar[1] = v0.y; ar[2] = v0.z; ar[3] = v0.w;
        ar[4] = v1.x; ar[5] = v1.y; ar[6] = v1.z; ar[7] = v1.w;
        const float4* pb = (const float4*)(wB + k0);
        float4 u0 = pb[0], u1 = pb[1];
        br[0] = u0.x; br[1] = u0.y; br[2] = u0.z; br[3] = u0.w;
        br[4] = u1.x; br[5] = u1.y; br[6] = u1.z; br[7] = u1.w;
    };
    auto store = [&](int s) {
#pragma unroll
        for (int j = 0; j < 8; j++) {           // A: transposed scatter
            __nv_bfloat16 h = __float2bfloat16(ar[j]);
            Ah[s][an + j][ac] = h;
            Al[s][an + j][ac] = __float2bfloat16(ar[j] - __bfloat162float(h));
        }
#pragma unroll
        for (int j = 0; j < 4; j++) {           // B: contiguous pairs
            __nv_bfloat16 h0 = __float2bfloat16(br[2 * j]);
            __nv_bfloat16 h1 = __float2bfloat16(br[2 * j + 1]);
            __nv_bfloat16 l0 = __float2bfloat16(br[2 * j] - __bfloat162float(h0));
            __nv_bfloat16 l1 = __float2bfloat16(br[2 * j + 1] - __bfloat162float(h1));
            *(__nv_bfloat162*)&Bh[s][bo][bk + 2 * j] = __halves2bfloat162(h0, h1);
            *(__nv_bfloat162*)&Bl[s][bo][bk + 2 * j] = __halves2bfloat162(l0, l1);
        }
    };

    load(0);
#pragma unroll 1
    for (int ks = 0; ks < KSTEPS; ks++) {
        int cur = ks & 1;
        store(cur);
        __syncthreads();
        if (ks + 1 < KSTEPS) load((ks + 1) * 16);
        mma_stage(acc, Ah[cur], Al[cur], Bh[cur], Bl[cur], wm0, wn0, lane);
    }

    // epilogue: g_w[b][n][o]
    const int r = lane >> 2, c2 = (lane & 3) * 2;
#pragma unroll
    for (int mi = 0; mi < 4; mi++)
#pragma unroll
        for (int ni = 0; ni < 4; ni++) {
            int n = n0 + wm0 + mi * 16 + r;
            int o = o0 + wn0 + ni * 8 + c2;
            float* p = g_w + ((size_t)(b * NTOK) + n) * CDIM + o;
            *(float2*)p = make_float2(acc[mi][ni][0], acc[mi][ni][1]);
            *(float2*)(p + 8 * CDIM) = make_float2(acc[mi][ni][2], acc[mi][ni][3]);
        }
}

// ===========================================================================
// K2: per (b,h,d): ninv = 1 / max( sum_n w^2 , 1e-24 )
// ===========================================================================
__global__ __launch_bounds__(256) void norm_kernel()
{
    const int bh = blockIdx.x;
    const int tid = threadIdx.x;
    const int d = tid & 63, g = tid >> 6;
    const int b = bh / NHEAD, h = bh % NHEAD;
    const float* base = g_w + (size_t)b * NTOK * CDIM + h * HDIM + d;
    float acc = 0.f;
    for (int n = g; n < NTOK; n += 4) {
        float v = base[(size_t)n * CDIM];
        acc += v * v;
    }
    __shared__ float red[256];
    red[tid] = acc;
    __syncthreads();
    if (g == 0) {
        float s = red[d] + red[d + 64] + red[d + 128] + red[d + 192];
        g_ninv[bh * HDIM + d] = 1.0f / fmaxf(s, 1e-24f);
    }
}

// ===========================================================================
// K3: per (b,n): s[h] = sum_d w^2 * ninv; Pi = softmax over heads of s*temp
// ===========================================================================
__global__ __launch_bounds__(256) void pi_kernel(const float* __restrict__ temp)
{
    const int t = blockIdx.x * 256 + threadIdx.x;
    const int b = t >> 10, n = t & 1023;
    const float4* wrow = (const float4*)(g_w + ((size_t)b * NTOK + n) * CDIM);
    const float4* nv   = (const float4*)(g_ninv + b * CDIM);

    float sv[NHEAD];
    float m = -1e30f;
#pragma unroll
    for (int h = 0; h < NHEAD; h++) {
        float a = 0.f;
#pragma unroll 4
        for (int q = 0; q < 16; q++) {
            float4 v = wrow[h * 16 + q];
            float4 u = nv[h * 16 + q];
            a += v.x * v.x * u.x + v.y * v.y * u.y
               + v.z * v.z * u.z + v.w * v.w * u.w;
        }
        sv[h] = a * temp[h];
        m = fmaxf(m, sv[h]);
    }
    float e[NHEAD];
    float sum = 0.f;
#pragma unroll
    for (int h = 0; h < NHEAD; h++) { e[h] = expf(sv[h] - m); sum += e[h]; }
    float inv = 1.0f / sum;
#pragma unroll
    for (int h = 0; h < NHEAD; h++)
        g_pi[((b * NHEAD + h) << 10) + n] = e[h] * inv;
}

// ===========================================================================
// K4: per (b,h): dots[d] = (sum_n Pi*w^2)/(sum_n Pi + 1e-8); attn = 1/(1+dots)
// ===========================================================================
__global__ __launch_bounds__(256) void attn_kernel()
{
    const int bh = blockIdx.x;
    const int tid = threadIdx.x;
    const int b = bh / NHEAD, h = bh % NHEAD;
    const float* pi = g_pi + bh * NTOK;

    __shared__ float red[256];
    float pp = 0.f;
    for (int n = tid; n < NTOK; n += 256) pp += pi[n];
    red[tid] = pp;
    __syncthreads();
    for (int s = 128; s > 0; s >>= 1) {
        if (tid < s) red[tid] += red[tid + s];
        __syncthreads();
    }
    float inv = 1.0f / (red[0] + 1e-8f);
    __syncthreads();

    const int d = tid & 63, g = tid >> 6;
    const float* base = g_w + (size_t)b * NTOK * CDIM + h * HDIM + d;
    float acc = 0.f;
    for (int n = g; n < NTOK; n += 4) {
        float v = base[(size_t)n * CDIM];
        acc += pi[n] * v * v;
    }
    red[tid] = acc;
    __syncthreads();
    if (g == 0) {
        float dots = (red[d] + red[d + 64] + red[d + 128] + red[d + 192]) * inv;
        g_attn[bh * HDIM + d] = 1.0f / (1.0f + dots);
    }
}

// ===========================================================================
// GEMM2: out[b,o,n] = sum_c out_w[o,c] * t[b,n,c] + out_b[o]
//   where t = -W * Pi[h(c),n] * attn[h(c),d(c)]  (fused into B-tile load).
//   M = o, N = n, K = c. Within a K=16 tile, h = k0>>6 is constant.
// ===========================================================================
__global__ __launch_bounds__(256) void gemm2_mma(
    const float* __restrict__ out_w, const float* __restrict__ out_b,
    float* __restrict__ out)
{
    __shared__ __nv_bfloat16 Ah[2][128][PITCH];
    __shared__ __nv_bfloat16 Al[2][128][PITCH];
    __shared__ __nv_bfloat16 Bh[2][128][PITCH];
    __shared__ __nv_bfloat16 Bl[2][128][PITCH];

    const int b   = blockIdx.z;
    const int n0  = blockIdx.x * 128;
    const int o0  = blockIdx.y * 128;
    const int tid = threadIdx.x;
    const int lane = tid & 31, wid = tid >> 5;
    const int wm0 = (wid >> 2) * 64;   // o-offset within block tile
    const int wn0 = (wid & 3) * 32;    // n-offset within block tile

    const int ao = tid >> 1;           // A: o row (0..127)
    const int ak = (tid & 1) * 8;      // A: k col
    const int bn = tid >> 1;           // B: n row (0..127)
    const int bk = (tid & 1) * 8;      // B: k col

    const float* wA = out_w + (size_t)(o0 + ao) * CDIM + ak;
    const float* gW = g_w + ((size_t)(b * NTOK) + n0 + bn) * CDIM + bk;

    float acc[4][4][4];
#pragma unroll
    for (int i = 0; i < 4; i++)
#pragma unroll
        for (int j = 0; j < 4; j++)
#pragma unroll
            for (int e = 0; e < 4; e++) acc[i][j][e] = 0.f;

    float ar[8], br[8];
    auto load = [&](int k0) {
        const float4* pa = (const float4*)(wA + k0);
        float4 v0 = pa[0], v1 = pa[1];
        ar[0] = v0.x; ar[1] = v0.y; ar[2] = v0.z; ar[3] = v0.w;
        ar[4] = v1.x; ar[5] = v1.y; ar[6] = v1.z; ar[7] = v1.w;
        const int h = k0 >> 6;
        const float npi = -g_pi[((b * NHEAD + h) << 10) + n0 + bn];
        const float* at = g_attn + (b * NHEAD + h) * HDIM + (k0 & 63) + bk;
        float4 a0 = *(const float4*)(at);
        float4 a1 = *(const float4*)(at + 4);
        const float4* pw = (const float4*)(gW + k0);
        float4 w0 = pw[0], w1 = pw[1];
        br[0] = w0.x * npi * a0.x; br[1] = w0.y * npi * a0.y;
        br[2] = w0.z * npi * a0.z; br[3] = w0.w * npi * a0.w;
        br[4] = w1.x * npi * a1.x; br[5] = w1.y * npi * a1.y;
        br[6] = w1.z * npi * a1.z; br[7] = w1.w * npi * a1.w;
    };
    auto store = [&](int s) {
#pragma unroll
        for (int j = 0; j < 4; j++) {
            __nv_bfloat16 h0 = __float2bfloat16(ar[2 * j]);
            __nv_bfloat16 h1 = __float2bfloat16(ar[2 * j + 1]);
            __nv_bfloat16 l0 = __float2bfloat16(ar[2 * j] - __bfloat162float(h0));
            __nv_bfloat16 l1 = __float2bfloat16(ar[2 * j + 1] - __bfloat162float(h1));
            *(__nv_bfloat162*)&Ah[s][ao][ak + 2 * j] = __halves2bfloat162(h0, h1);
            *(__nv_bfloat162*)&Al[s][ao][ak + 2 * j] = __halves2bfloat162(l0, l1);
        }
#pragma unroll
        for (int j = 0; j < 4; j++) {
            __nv_bfloat16 h0 = __float2bfloat16(br[2 * j]);
            __nv_bfloat16 h1 = __float2bfloat16(br[2 * j + 1]);
            __nv_bfloat16 l0 = __float2bfloat16(br[2 * j] - __bfloat162float(h0));
            __nv_bfloat16 l1 = __float2bfloat16(br[2 * j + 1] - __bfloat162float(h1));
            *(__nv_bfloat162*)&Bh[s][bn][bk + 2 * j] = __halves2bfloat162(h0, h1);
            *(__nv_bfloat162*)&Bl[s][bn][bk + 2 * j] = __halves2bfloat162(l0, l1);
        }
    };

    load(0);
#pragma unroll 1
    for (int ks = 0; ks < KSTEPS; ks++) {
        int cur = ks & 1;
        store(cur);
        __syncthreads();
        if (ks + 1 < KSTEPS) load((ks + 1) * 16);
        mma_stage(acc, Ah[cur], Al[cur], Bh[cur], Bl[cur], wm0, wn0, lane);
    }

    // epilogue: out[b][o][n] + bias
    const int r = lane >> 2, c2 = (lane & 3) * 2;
#pragma unroll
    for (int mi = 0; mi < 4; mi++)
#pragma unroll
        for (int ni = 0; ni < 4; ni++) {
            int o = o0 + wm0 + mi * 16 + r;
            int n = n0 + wn0 + ni * 8 + c2;
            float b0 = out_b[o], b1 = out_b[o + 8];
            float* p = out + ((size_t)(b * CDIM) + o) * NTOK + n;
            *(float2*)p = make_float2(acc[mi][ni][0] + b0, acc[mi][ni][1] + b0);
            *(float2*)(p + 8 * NTOK) =
                make_float2(acc[mi][ni][2] + b1, acc[mi][ni][3] + b1);
        }
}

// ===========================================================================
extern "C" void kernel_launch(void* const* d_in, const int* in_sizes, int n_in,
                              void* d_out, int out_size)
{
    const float* x     = (const float*)d_in[0];   // [32, 768, 32, 32]
    const float* qkv_w = (const float*)d_in[1];   // [768, 768]
    const float* temp  = (const float*)d_in[2];   // [12, 1]
    const float* out_w = (const float*)d_in[3];   // [768, 768]
    const float* out_b = (const float*)d_in[4];   // [768]
    float* out = (float*)d_out;                   // [32, 768, 32, 32]

    dim3 g(NTOK / 128, CDIM / 128, BATCH);        // 8 x 6 x 32
    gemm1_mma<<<g, 256>>>(x, qkv_w);
    norm_kernel<<<BATCH * NHEAD, 256>>>();
    pi_kernel<<<(BATCH * NTOK) / 256, 256>>>(temp);
    attn_kernel<<<BATCH * NHEAD, 256>>>();
    gemm2_mma<<<g, 256>>>(out_w, out_b, out);
}

// round 8
// speedup vs baseline: 1.6785x; 1.6306x over previous
#include <cuda_runtime.h>
#include <cuda_bf16.h>
#include <cstdint>

#define BATCH 32
#define CDIM  768
#define NTOK  1024
#define NHEAD 12
#define HDIM  64

#define KS     32                 // K per stage
#define NSTAGE (CDIM / KS)        // 24
#define PITCHE 40                 // bf16 elems per smem row (32 data + 8 pad)
#define ASZ    (128 * PITCHE * 2) // bytes per tile array (10240)
#define BUFB   (4 * ASZ)          // bytes per stage buffer (40960)
#define SMEM_DYN (2 * BUFB)       // 81920

// ---------------------------------------------------------------------------
// Global scratch (no allocations allowed)
// ---------------------------------------------------------------------------
__device__ float g_w[(size_t)BATCH * NTOK * CDIM];      // W[b,n,c] fp32
__device__ float g_ninv[BATCH * NHEAD * HDIM];
__device__ float g_pi[BATCH * NHEAD * NTOK];
__device__ float g_attn[BATCH * NHEAD * HDIM];
__device__ __nv_bfloat16 g_xh[(size_t)BATCH * NTOK * CDIM];  // x^T hi
__device__ __nv_bfloat16 g_xl[(size_t)BATCH * NTOK * CDIM];  // x^T lo
__device__ __nv_bfloat16 g_th[(size_t)BATCH * NTOK * CDIM];  // t hi
__device__ __nv_bfloat16 g_tl[(size_t)BATCH * NTOK * CDIM];  // t lo
__device__ __nv_bfloat16 g_qwh[CDIM * CDIM], g_qwl[CDIM * CDIM];
__device__ __nv_bfloat16 g_owh[CDIM * CDIM], g_owl[CDIM * CDIM];

// ---------------------------------------------------------------------------
// helpers
// ---------------------------------------------------------------------------
__device__ __forceinline__ uint32_t smem_u32(const void* p) {
    return (uint32_t)__cvta_generic_to_shared(p);
}
__device__ __forceinline__ void ldmatrix_x4(unsigned& r0, unsigned& r1,
                                            unsigned& r2, unsigned& r3, uint32_t a) {
    asm volatile("ldmatrix.sync.aligned.m8n8.x4.shared.b16 {%0,%1,%2,%3}, [%4];"
                 : "=r"(r0), "=r"(r1), "=r"(r2), "=r"(r3) : "r"(a));
}
__device__ __forceinline__ void ldmatrix_x2(unsigned& r0, unsigned& r1, uint32_t a) {
    asm volatile("ldmatrix.sync.aligned.m8n8.x2.shared.b16 {%0,%1}, [%2];"
                 : "=r"(r0), "=r"(r1) : "r"(a));
}
__device__ __forceinline__ void mma16816(float* c, const unsigned* a, const unsigned* b) {
    asm volatile(
        "mma.sync.aligned.m16n8k16.row.col.f32.bf16.bf16.f32 "
        "{%0,%1,%2,%3}, {%4,%5,%6,%7}, {%8,%9}, {%0,%1,%2,%3};"
        : "+f"(c[0]), "+f"(c[1]), "+f"(c[2]), "+f"(c[3])
        : "r"(a[0]), "r"(a[1]), "r"(a[2]), "r"(a[3]), "r"(b[0]), "r"(b[1]));
}
#define CP16(dst, src) \
    asm volatile("cp.async.cg.shared.global [%0], [%1], 16;" \
                 :: "r"(dst), "l"(src) : "memory")
#define CP_COMMIT() asm volatile("cp.async.commit_group;" ::: "memory")
#define CP_WAIT(n)  asm volatile("cp.async.wait_group %0;" :: "n"(n) : "memory")

__device__ __forceinline__ void split1(float v, __nv_bfloat16& h, __nv_bfloat16& l) {
    h = __float2bfloat16(v);
    l = __float2bfloat16(v - __bfloat162float(h));
}

// ---------------------------------------------------------------------------
// Split kernels
// ---------------------------------------------------------------------------
// x[b,c,n] fp32 -> g_xh/g_xl[b,n,c] bf16 (transpose fused)
__global__ __launch_bounds__(256) void split_x_kernel(const float* __restrict__ x)
{
    __shared__ float sm[32][33];
    const int b = blockIdx.z, c0 = blockIdx.y * 32, n0 = blockIdx.x * 32;
    const int tj = threadIdx.x & 31, ti = threadIdx.x >> 5;   // ti: 0..7
    const float* xp = x + ((size_t)b * CDIM + c0 + ti) * NTOK + n0 + tj;
#pragma unroll
    for (int k = 0; k < 4; k++)
        sm[ti + k * 8][tj] = xp[(size_t)k * 8 * NTOK];
    __syncthreads();
#pragma unroll
    for (int k = 0; k < 4; k++) {
        float v = sm[tj][ti + k * 8];
        __nv_bfloat16 h, l;
        split1(v, h, l);
        size_t idx = ((size_t)(b * NTOK) + n0 + ti + k * 8) * CDIM + c0 + tj;
        g_xh[idx] = h;
        g_xl[idx] = l;
    }
}

// weight split: which=0 -> qkv_w, which=1 -> out_w
__global__ __launch_bounds__(256) void split_w_kernel(const float* __restrict__ w, int which)
{
    const int t = blockIdx.x * 256 + threadIdx.x;   // 147456 float4s
    __nv_bfloat16* hh = which ? g_owh : g_qwh;
    __nv_bfloat16* ll = which ? g_owl : g_qwl;
    float4 v = ((const float4*)w)[t];
    __nv_bfloat16 h0, l0, h1, l1, h2, l2, h3, l3;
    split1(v.x, h0, l0); split1(v.y, h1, l1);
    split1(v.z, h2, l2); split1(v.w, h3, l3);
    *(__nv_bfloat162*)&hh[t * 4]     = __halves2bfloat162(h0, h1);
    *(__nv_bfloat162*)&hh[t * 4 + 2] = __halves2bfloat162(h2, h3);
    *(__nv_bfloat162*)&ll[t * 4]     = __halves2bfloat162(l0, l1);
    *(__nv_bfloat162*)&ll[t * 4 + 2] = __halves2bfloat162(l2, l3);
}

// t = -W * Pi[h,n] * attn[h,d]  -> g_th/g_tl[b,n,c]
__global__ __launch_bounds__(256) void split_t_kernel()
{
    const int flat = blockIdx.x * 256 + threadIdx.x;  // < 32*1024*192
    const int row = flat / 192;                       // b*1024 + n
    const int c4 = flat - row * 192;
    const int b = row >> 10, n = row & 1023;
    const int h = c4 >> 4;
    const int d = (c4 & 15) * 4;
    const float npi = -g_pi[((b * NHEAD + h) << 10) + n];
    const float4 at = *(const float4*)&g_attn[(b * NHEAD + h) * HDIM + d];
    const float4 v = *(const float4*)&g_w[(size_t)row * CDIM + c4 * 4];
    float t0 = v.x * npi * at.x, t1 = v.y * npi * at.y;
    float t2 = v.z * npi * at.z, t3 = v.w * npi * at.w;
    __nv_bfloat16 h0, l0, h1, l1, h2, l2, h3, l3;
    split1(t0, h0, l0); split1(t1, h1, l1);
    split1(t2, h2, l2); split1(t3, h3, l3);
    size_t idx = (size_t)row * CDIM + c4 * 4;
    *(__nv_bfloat162*)&g_th[idx]     = __halves2bfloat162(h0, h1);
    *(__nv_bfloat162*)&g_th[idx + 2] = __halves2bfloat162(h2, h3);
    *(__nv_bfloat162*)&g_tl[idx]     = __halves2bfloat162(l0, l1);
    *(__nv_bfloat162*)&g_tl[idx + 2] = __halves2bfloat162(l2, l3);
}

// ---------------------------------------------------------------------------
// HMMA mainloop core: D[128x128] += A[128xK]*B[128xK]^T, 3-term bf16 split.
// A,B pre-split in global; cp.async staged, double buffered, K=32 stages.
// ---------------------------------------------------------------------------
__device__ __forceinline__ void hmma_stage(
    float acc[4][4][4], const char* buf, int wm0, int wn0, int lane)
{
    const int ar = wm0 + (lane & 15);
    const int ac = ((lane >> 4) & 1) * 8;
    const int br = wn0 + (lane & 7);
    const int bc = ((lane >> 3) & 1) * 8;
    const uint32_t sAh = smem_u32(buf);
    const uint32_t sAl = sAh + ASZ;
    const uint32_t sBh = sAh + 2 * ASZ;
    const uint32_t sBl = sAh + 3 * ASZ;
#pragma unroll
    for (int kc = 0; kc < 2; kc++) {
        unsigned ah[4][4], al[4][4], bh[4][2], bl[4][2];
#pragma unroll
        for (int mi = 0; mi < 4; mi++) {
            uint32_t off = ((ar + mi * 16) * PITCHE + kc * 16 + ac) * 2;
            ldmatrix_x4(ah[mi][0], ah[mi][1], ah[mi][2], ah[mi][3], sAh + off);
            ldmatrix_x4(al[mi][0], al[mi][1], al[mi][2], al[mi][3], sAl + off);
        }
#pragma unroll
        for (int ni = 0; ni < 4; ni++) {
            uint32_t off = ((br + ni * 8) * PITCHE + kc * 16 + bc) * 2;
            ldmatrix_x2(bh[ni][0], bh[ni][1], sBh + off);
            ldmatrix_x2(bl[ni][0], bl[ni][1], sBl + off);
        }
#pragma unroll
        for (int mi = 0; mi < 4; mi++)
#pragma unroll
            for (int ni = 0; ni < 4; ni++) {
                mma16816(acc[mi][ni], ah[mi], bh[ni]);
                mma16816(acc[mi][ni], ah[mi], bl[ni]);
                mma16816(acc[mi][ni], al[mi], bh[ni]);
            }
    }
}

__device__ __forceinline__ void hmma_mainloop(
    float acc[4][4][4],
    const __nv_bfloat16* __restrict__ Ah, const __nv_bfloat16* __restrict__ Al,
    const __nv_bfloat16* __restrict__ Bh, const __nv_bfloat16* __restrict__ Bl,
    char* smp, int wm0, int wn0, int lane)
{
    const int tid = threadIdx.x;
    const int row = tid >> 1;            // 0..127
    const int khe = (tid & 1) * 16;      // k elem offset within stage

    const __nv_bfloat16* gA[2] = { Ah + (size_t)row * CDIM + khe,
                                   Al + (size_t)row * CDIM + khe };
    const __nv_bfloat16* gB[2] = { Bh + (size_t)row * CDIM + khe,
                                   Bl + (size_t)row * CDIM + khe };
    const uint32_t sdst = smem_u32(smp) + row * (PITCHE * 2) + khe * 2;

    auto issue = [&](int s) {
        const uint32_t d = sdst + (s & 1) * BUFB;
        const int k0 = s * KS;
#pragma unroll
        for (int a = 0; a < 2; a++) {
            CP16(d + a * ASZ,           gA[a] + k0);
            CP16(d + a * ASZ + 16,      gA[a] + k0 + 8);
            CP16(d + (a + 2) * ASZ,     gB[a] + k0);
            CP16(d + (a + 2) * ASZ + 16, gB[a] + k0 + 8);
        }
        CP_COMMIT();
    };

    issue(0);
#pragma unroll 1
    for (int s = 0; s < NSTAGE; s++) {
        if (s + 1 < NSTAGE) {
            issue(s + 1);
            CP_WAIT(1);
        } else {
            CP_WAIT(0);
        }
        __syncthreads();
        hmma_stage(acc, smp + (s & 1) * BUFB, wm0, wn0, lane);
        __syncthreads();
    }
}

// GEMM1: g_w[b, n, o] = sum_c x^T[n,c] * qkv_w[o,c]   (M=n, N=o)
__global__ __launch_bounds__(256) void gemm1_hmma()
{
    extern __shared__ char smp[];
    const int tid = threadIdx.x, lane = tid & 31, wid = tid >> 5;
    const int b = blockIdx.z, n0 = blockIdx.x * 128, o0 = blockIdx.y * 128;
    const int wm0 = (wid >> 2) * 64, wn0 = (wid & 3) * 32;

    float acc[4][4][4];
#pragma unroll
    for (int i = 0; i < 4; i++)
#pragma unroll
        for (int j = 0; j < 4; j++)
#pragma unroll
            for (int e = 0; e < 4; e++) acc[i][j][e] = 0.f;

    const size_t arow = (size_t)(b * NTOK + n0) * CDIM;
    hmma_mainloop(acc, g_xh + arow, g_xl + arow,
                  g_qwh + (size_t)o0 * CDIM, g_qwl + (size_t)o0 * CDIM,
                  smp, wm0, wn0, lane);

    const int r = lane >> 2, c2 = (lane & 3) * 2;
#pragma unroll
    for (int mi = 0; mi < 4; mi++)
#pragma unroll
        for (int ni = 0; ni < 4; ni++) {
            int n = n0 + wm0 + mi * 16 + r;
            int o = o0 + wn0 + ni * 8 + c2;
            float* p = g_w + ((size_t)(b * NTOK) + n) * CDIM + o;
            *(float2*)p = make_float2(acc[mi][ni][0], acc[mi][ni][1]);
            *(float2*)(p + 8 * CDIM) = make_float2(acc[mi][ni][2], acc[mi][ni][3]);
        }
}

// GEMM2: out[b, o, n] = sum_c out_w[o,c] * t[n,c] + out_b[o]   (M=o, N=n)
__global__ __launch_bounds__(256) void gemm2_hmma(
    const float* __restrict__ out_b, float* __restrict__ out)
{
    extern __shared__ char smp[];
    const int tid = threadIdx.x, lane = tid & 31, wid = tid >> 5;
    const int b = blockIdx.z, n0 = blockIdx.x * 128, o0 = blockIdx.y * 128;
    const int wm0 = (wid >> 2) * 64, wn0 = (wid & 3) * 32;

    float acc[4][4][4];
#pragma unroll
    for (int i = 0; i < 4; i++)
#pragma unroll
        for (int j = 0; j < 4; j++)
#pragma unroll
            for (int e = 0; e < 4; e++) acc[i][j][e] = 0.f;

    const size_t brow = (size_t)(b * NTOK + n0) * CDIM;
    hmma_mainloop(acc, g_owh + (size_t)o0 * CDIM, g_owl + (size_t)o0 * CDIM,
                  g_th + brow, g_tl + brow,
                  smp, wm0, wn0, lane);

    const int r = lane >> 2, c2 = (lane & 3) * 2;
#pragma unroll
    for (int mi = 0; mi < 4; mi++)
#pragma unroll
        for (int ni = 0; ni < 4; ni++) {
            int o = o0 + wm0 + mi * 16 + r;
            int n = n0 + wn0 + ni * 8 + c2;
            float b0 = out_b[o], b1 = out_b[o + 8];
            float* p = out + ((size_t)(b * CDIM) + o) * NTOK + n;
            *(float2*)p = make_float2(acc[mi][ni][0] + b0, acc[mi][ni][1] + b0);
            *(float2*)(p + 8 * NTOK) =
                make_float2(acc[mi][ni][2] + b1, acc[mi][ni][3] + b1);
        }
}

// ---------------------------------------------------------------------------
// Middle kernels (unchanged)
// ---------------------------------------------------------------------------
__global__ __launch_bounds__(256) void norm_kernel()
{
    const int bh = blockIdx.x;
    const int tid = threadIdx.x;
    const int d = tid & 63, g = tid >> 6;
    const int b = bh / NHEAD, h = bh % NHEAD;
    const float* base = g_w + (size_t)b * NTOK * CDIM + h * HDIM + d;
    float acc = 0.f;
    for (int n = g; n < NTOK; n += 4) {
        float v = base[(size_t)n * CDIM];
        acc += v * v;
    }
    __shared__ float red[256];
    red[tid] = acc;
    __syncthreads();
    if (g == 0) {
        float s = red[d] + red[d + 64] + red[d + 128] + red[d + 192];
        g_ninv[bh * HDIM + d] = 1.0f / fmaxf(s, 1e-24f);
    }
}

__global__ __launch_bounds__(256) void pi_kernel(const float* __restrict__ temp)
{
    const int t = blockIdx.x * 256 + threadIdx.x;
    const int b = t >> 10, n = t & 1023;
    const float4* wrow = (const float4*)(g_w + ((size_t)b * NTOK + n) * CDIM);
    const float4* nv = (const float4*)(g_ninv + b * CDIM);

    float sv[NHEAD];
    float m = -1e30f;
#pragma unroll
    for (int h = 0; h < NHEAD; h++) {
        float a = 0.f;
#pragma unroll 4
        for (int q = 0; q < 16; q++) {
            float4 v = wrow[h * 16 + q];
            float4 u = nv[h * 16 + q];
            a += v.x * v.x * u.x + v.y * v.y * u.y + v.z * v.z * u.z + v.w * v.w * u.w;
        }
        sv[h] = a * temp[h];
        m = fmaxf(m, sv[h]);
    }
    float e[NHEAD];
    float sum = 0.f;
#pragma unroll
    for (int h = 0; h < NHEAD; h++) { e[h] = expf(sv[h] - m); sum += e[h]; }
    float inv = 1.0f / sum;
#pragma unroll
    for (int h = 0; h < NHEAD; h++)
        g_pi[((b * NHEAD + h) << 10) + n] = e[h] * inv;
}

__global__ __launch_bounds__(256) void attn_kernel()
{
    const int bh = blockIdx.x;
    const int tid = threadIdx.x;
    const int b = bh / NHEAD, h = bh % NHEAD;
    const float* pi = g_pi + bh * NTOK;

    __shared__ float red[256];
    float pp = 0.f;
    for (int n = tid; n < NTOK; n += 256) pp += pi[n];
    red[tid] = pp;
    __syncthreads();
    for (int s = 128; s > 0; s >>= 1) {
        if (tid < s) red[tid] += red[tid + s];
        __syncthreads();
    }
    float inv = 1.0f / (red[0] + 1e-8f);
    __syncthreads();

    const int d = tid & 63, g = tid >> 6;
    const float* base = g_w + (size_t)b * NTOK * CDIM + h * HDIM + d;
    float acc = 0.f;
    for (int n = g; n < NTOK; n += 4) {
        float v = base[(size_t)n * CDIM];
        acc += pi[n] * v * v;
    }
    red[tid] = acc;
    __syncthreads();
    if (g == 0) {
        float dots = (red[d] + red[d + 64] + red[d + 128] + red[d + 192]) * inv;
        g_attn[bh * HDIM + d] = 1.0f / (1.0f + dots);
    }
}

// ---------------------------------------------------------------------------
extern "C" void kernel_launch(void* const* d_in, const int* in_sizes, int n_in,
                              void* d_out, int out_size)
{
    const float* x     = (const float*)d_in[0];
    const float* qkv_w = (const float*)d_in[1];
    const float* temp  = (const float*)d_in[2];
    const float* out_w = (const float*)d_in[3];
    const float* out_b = (const float*)d_in[4];
    float* out = (float*)d_out;

    cudaFuncSetAttribute(gemm1_hmma, cudaFuncAttributeMaxDynamicSharedMemorySize, SMEM_DYN);
    cudaFuncSetAttribute(gemm2_hmma, cudaFuncAttributeMaxDynamicSharedMemorySize, SMEM_DYN);

    split_x_kernel<<<dim3(NTOK / 32, CDIM / 32, BATCH), 256>>>(x);
    split_w_kernel<<<(CDIM * CDIM / 4) / 256, 256>>>(qkv_w, 0);
    split_w_kernel<<<(CDIM * CDIM / 4) / 256, 256>>>(out_w, 1);

    dim3 g(NTOK / 128, CDIM / 128, BATCH);   // 8 x 6 x 32
    gemm1_hmma<<<g, 256, SMEM_DYN>>>();

    norm_kernel<<<BATCH * NHEAD, 256>>>();
    pi_kernel<<<(BATCH * NTOK) / 256, 256>>>(temp);
    attn_kernel<<<BATCH * NHEAD, 256>>>();

    split_t_kernel<<<(BATCH * NTOK * (CDIM / 4)) / 256, 256>>>();

    gemm2_hmma<<<g, 256, SMEM_DYN>>>(out_b, out);
}

// round 9
// speedup vs baseline: 1.6826x; 1.0024x over previous
#include <cuda_runtime.h>
#include <cuda_bf16.h>
#include <cstdint>

#define BATCH 32
#define CDIM  768
#define NTOK  1024
#define NHEAD 12
#define HDIM  64

#define KS     16                 // K per stage
#define NSTAGE (CDIM / KS)        // 48
#define NBUF   4
#define PITCHE 24                 // bf16 elems per smem row (16 data + 8 pad)
#define ASZ    (128 * PITCHE * 2) // bytes per tile array (6144)
#define BUFB   (4 * ASZ)          // bytes per stage buffer (24576)
#define SMEM_DYN (NBUF * BUFB)    // 98304

// ---------------------------------------------------------------------------
// Global scratch (no allocations allowed)
// ---------------------------------------------------------------------------
__device__ float g_w[(size_t)BATCH * NTOK * CDIM];      // W[b,n,c] fp32
__device__ float g_ninv[BATCH * NHEAD * HDIM];
__device__ float g_pi[BATCH * NHEAD * NTOK];
__device__ float g_attn[BATCH * NHEAD * HDIM];
__device__ __nv_bfloat16 g_xh[(size_t)BATCH * NTOK * CDIM];  // x^T hi
__device__ __nv_bfloat16 g_xl[(size_t)BATCH * NTOK * CDIM];  // x^T lo
__device__ __nv_bfloat16 g_th[(size_t)BATCH * NTOK * CDIM];  // t hi
__device__ __nv_bfloat16 g_tl[(size_t)BATCH * NTOK * CDIM];  // t lo
__device__ __nv_bfloat16 g_qwh[CDIM * CDIM], g_qwl[CDIM * CDIM];
__device__ __nv_bfloat16 g_owh[CDIM * CDIM], g_owl[CDIM * CDIM];

// ---------------------------------------------------------------------------
// helpers
// ---------------------------------------------------------------------------
__device__ __forceinline__ uint32_t smem_u32(const void* p) {
    return (uint32_t)__cvta_generic_to_shared(p);
}
__device__ __forceinline__ void ldmatrix_x4(unsigned& r0, unsigned& r1,
                                            unsigned& r2, unsigned& r3, uint32_t a) {
    asm volatile("ldmatrix.sync.aligned.m8n8.x4.shared.b16 {%0,%1,%2,%3}, [%4];"
                 : "=r"(r0), "=r"(r1), "=r"(r2), "=r"(r3) : "r"(a));
}
__device__ __forceinline__ void ldmatrix_x2(unsigned& r0, unsigned& r1, uint32_t a) {
    asm volatile("ldmatrix.sync.aligned.m8n8.x2.shared.b16 {%0,%1}, [%2];"
                 : "=r"(r0), "=r"(r1) : "r"(a));
}
__device__ __forceinline__ void mma16816(float* c, const unsigned* a, const unsigned* b) {
    asm volatile(
        "mma.sync.aligned.m16n8k16.row.col.f32.bf16.bf16.f32 "
        "{%0,%1,%2,%3}, {%4,%5,%6,%7}, {%8,%9}, {%0,%1,%2,%3};"
        : "+f"(c[0]), "+f"(c[1]), "+f"(c[2]), "+f"(c[3])
        : "r"(a[0]), "r"(a[1]), "r"(a[2]), "r"(a[3]), "r"(b[0]), "r"(b[1]));
}
#define CP16(dst, src) \
    asm volatile("cp.async.cg.shared.global [%0], [%1], 16;" \
                 :: "r"(dst), "l"(src) : "memory")
#define CP_COMMIT() asm volatile("cp.async.commit_group;" ::: "memory")
#define CP_WAIT(n)  asm volatile("cp.async.wait_group %0;" :: "n"(n) : "memory")

__device__ __forceinline__ void split1(float v, __nv_bfloat16& h, __nv_bfloat16& l) {
    h = __float2bfloat16(v);
    l = __float2bfloat16(v - __bfloat162float(h));
}

// ---------------------------------------------------------------------------
// Split kernels
// ---------------------------------------------------------------------------
// x[b,c,n] fp32 -> g_xh/g_xl[b,n,c] bf16 (transpose fused)
__global__ __launch_bounds__(256) void split_x_kernel(const float* __restrict__ x)
{
    __shared__ float sm[32][33];
    const int b = blockIdx.z, c0 = blockIdx.y * 32, n0 = blockIdx.x * 32;
    const int tj = threadIdx.x & 31, ti = threadIdx.x >> 5;   // ti: 0..7
    const float* xp = x + ((size_t)b * CDIM + c0 + ti) * NTOK + n0 + tj;
#pragma unroll
    for (int k = 0; k < 4; k++)
        sm[ti + k * 8][tj] = xp[(size_t)k * 8 * NTOK];
    __syncthreads();
#pragma unroll
    for (int k = 0; k < 4; k++) {
        float v = sm[tj][ti + k * 8];
        __nv_bfloat16 h, l;
        split1(v, h, l);
        size_t idx = ((size_t)(b * NTOK) + n0 + ti + k * 8) * CDIM + c0 + tj;
        g_xh[idx] = h;
        g_xl[idx] = l;
    }
}

// weight split: which=0 -> qkv_w, which=1 -> out_w
__global__ __launch_bounds__(256) void split_w_kernel(const float* __restrict__ w, int which)
{
    const int t = blockIdx.x * 256 + threadIdx.x;   // 147456 float4s
    __nv_bfloat16* hh = which ? g_owh : g_qwh;
    __nv_bfloat16* ll = which ? g_owl : g_qwl;
    float4 v = ((const float4*)w)[t];
    __nv_bfloat16 h0, l0, h1, l1, h2, l2, h3, l3;
    split1(v.x, h0, l0); split1(v.y, h1, l1);
    split1(v.z, h2, l2); split1(v.w, h3, l3);
    *(__nv_bfloat162*)&hh[t * 4]     = __halves2bfloat162(h0, h1);
    *(__nv_bfloat162*)&hh[t * 4 + 2] = __halves2bfloat162(h2, h3);
    *(__nv_bfloat162*)&ll[t * 4]     = __halves2bfloat162(l0, l1);
    *(__nv_bfloat162*)&ll[t * 4 + 2] = __halves2bfloat162(l2, l3);
}

// t = -W * Pi[h,n] * attn[h,d]  -> g_th/g_tl[b,n,c]
__global__ __launch_bounds__(256) void split_t_kernel()
{
    const int flat = blockIdx.x * 256 + threadIdx.x;  // < 32*1024*192
    const int row = flat / 192;                       // b*1024 + n
    const int c4 = flat - row * 192;
    const int b = row >> 10, n = row & 1023;
    const int h = c4 >> 4;
    const int d = (c4 & 15) * 4;
    const float npi = -g_pi[((b * NHEAD + h) << 10) + n];
    const float4 at = *(const float4*)&g_attn[(b * NHEAD + h) * HDIM + d];
    const float4 v = *(const float4*)&g_w[(size_t)row * CDIM + c4 * 4];
    float t0 = v.x * npi * at.x, t1 = v.y * npi * at.y;
    float t2 = v.z * npi * at.z, t3 = v.w * npi * at.w;
    __nv_bfloat16 h0, l0, h1, l1, h2, l2, h3, l3;
    split1(t0, h0, l0); split1(t1, h1, l1);
    split1(t2, h2, l2); split1(t3, h3, l3);
    size_t idx = (size_t)row * CDIM + c4 * 4;
    *(__nv_bfloat162*)&g_th[idx]     = __halves2bfloat162(h0, h1);
    *(__nv_bfloat162*)&g_th[idx + 2] = __halves2bfloat162(h2, h3);
    *(__nv_bfloat162*)&g_tl[idx]     = __halves2bfloat162(l0, l1);
    *(__nv_bfloat162*)&g_tl[idx + 2] = __halves2bfloat162(l2, l3);
}

// ---------------------------------------------------------------------------
// HMMA mainloop: D[128x128] += A[128xK]*B[128xK]^T, 3-term bf16 split.
// KS=16 stages, 4 buffers, prefetch depth 3, ONE __syncthreads per stage.
// Group-count invariant: exactly one commit_group per iteration (empty at
// tail), so wait_group 2 always retires exactly stage s's data.
// ---------------------------------------------------------------------------
__device__ __forceinline__ void hmma_stage(
    float acc[4][4][4], uint32_t sbase, int wm0, int wn0, int lane)
{
    const int ar = wm0 + (lane & 15);
    const int ac = ((lane >> 4) & 1) * 8;
    const int br = wn0 + (lane & 7);
    const int bc = ((lane >> 3) & 1) * 8;
    const uint32_t sAh = sbase;
    const uint32_t sAl = sbase + ASZ;
    const uint32_t sBh = sbase + 2 * ASZ;
    const uint32_t sBl = sbase + 3 * ASZ;

    unsigned ah[4][4], al[4][4], bh[4][2], bl[4][2];
#pragma unroll
    for (int mi = 0; mi < 4; mi++) {
        uint32_t off = ((ar + mi * 16) * PITCHE + ac) * 2;
        ldmatrix_x4(ah[mi][0], ah[mi][1], ah[mi][2], ah[mi][3], sAh + off);
        ldmatrix_x4(al[mi][0], al[mi][1], al[mi][2], al[mi][3], sAl + off);
    }
#pragma unroll
    for (int ni = 0; ni < 4; ni++) {
        uint32_t off = ((br + ni * 8) * PITCHE + bc) * 2;
        ldmatrix_x2(bh[ni][0], bh[ni][1], sBh + off);
        ldmatrix_x2(bl[ni][0], bl[ni][1], sBl + off);
    }
#pragma unroll
    for (int mi = 0; mi < 4; mi++)
#pragma unroll
        for (int ni = 0; ni < 4; ni++) {
            mma16816(acc[mi][ni], ah[mi], bh[ni]);
            mma16816(acc[mi][ni], ah[mi], bl[ni]);
            mma16816(acc[mi][ni], al[mi], bh[ni]);
        }
}

__device__ __forceinline__ void hmma_mainloop(
    float acc[4][4][4],
    const __nv_bfloat16* __restrict__ Ah, const __nv_bfloat16* __restrict__ Al,
    const __nv_bfloat16* __restrict__ Bh, const __nv_bfloat16* __restrict__ Bl,
    char* smp, int wm0, int wn0, int lane)
{
    const int tid = threadIdx.x;
    const int row = tid >> 1;            // 0..127
    const int khe = (tid & 1) * 8;       // k elem offset (16B) within stage

    const __nv_bfloat16* gA0 = Ah + (size_t)row * CDIM + khe;
    const __nv_bfloat16* gA1 = Al + (size_t)row * CDIM + khe;
    const __nv_bfloat16* gB0 = Bh + (size_t)row * CDIM + khe;
    const __nv_bfloat16* gB1 = Bl + (size_t)row * CDIM + khe;
    const uint32_t sdst = smem_u32(smp) + row * (PITCHE * 2) + khe * 2;
    const uint32_t sbase0 = smem_u32(smp);

    auto issue = [&](int s) {
        const uint32_t d = sdst + (s & (NBUF - 1)) * BUFB;
        const int k0 = s * KS;
        CP16(d,           gA0 + k0);
        CP16(d + ASZ,     gA1 + k0);
        CP16(d + 2 * ASZ, gB0 + k0);
        CP16(d + 3 * ASZ, gB1 + k0);
        CP_COMMIT();
    };

    issue(0);
    issue(1);
    issue(2);
#pragma unroll 1
    for (int s = 0; s < NSTAGE; s++) {
        CP_WAIT(2);            // stage s's group retired (invariant: 1 commit/iter)
        __syncthreads();       // all warps done with compute(s-1) AND see stage-s data
        if (s + 3 < NSTAGE) issue(s + 3);   // writes buffer (s-1)&3 — freed by the sync
        else CP_COMMIT();                    // empty group keeps the count invariant
        hmma_stage(acc, sbase0 + (s & (NBUF - 1)) * BUFB, wm0, wn0, lane);
    }
}

// GEMM1: g_w[b, n, o] = sum_c x^T[n,c] * qkv_w[o,c]   (M=n, N=o)
__global__ __launch_bounds__(256, 2) void gemm1_hmma()
{
    extern __shared__ char smp[];
    const int tid = threadIdx.x, lane = tid & 31, wid = tid >> 5;
    const int b = blockIdx.z, n0 = blockIdx.x * 128, o0 = blockIdx.y * 128;
    const int wm0 = (wid >> 2) * 64, wn0 = (wid & 3) * 32;

    float acc[4][4][4];
#pragma unroll
    for (int i = 0; i < 4; i++)
#pragma unroll
        for (int j = 0; j < 4; j++)
#pragma unroll
            for (int e = 0; e < 4; e++) acc[i][j][e] = 0.f;

    const size_t arow = (size_t)(b * NTOK + n0) * CDIM;
    hmma_mainloop(acc, g_xh + arow, g_xl + arow,
                  g_qwh + (size_t)o0 * CDIM, g_qwl + (size_t)o0 * CDIM,
                  smp, wm0, wn0, lane);

    const int r = lane >> 2, c2 = (lane & 3) * 2;
#pragma unroll
    for (int mi = 0; mi < 4; mi++)
#pragma unroll
        for (int ni = 0; ni < 4; ni++) {
            int n = n0 + wm0 + mi * 16 + r;
            int o = o0 + wn0 + ni * 8 + c2;
            float* p = g_w + ((size_t)(b * NTOK) + n) * CDIM + o;
            *(float2*)p = make_float2(acc[mi][ni][0], acc[mi][ni][1]);
            *(float2*)(p + 8 * CDIM) = make_float2(acc[mi][ni][2], acc[mi][ni][3]);
        }
}

// GEMM2: out[b, o, n] = sum_c out_w[o,c] * t[n,c] + out_b[o]   (M=o, N=n)
__global__ __launch_bounds__(256, 2) void gemm2_hmma(
    const float* __restrict__ out_b, float* __restrict__ out)
{
    extern __shared__ char smp[];
    const int tid = threadIdx.x, lane = tid & 31, wid = tid >> 5;
    const int b = blockIdx.z, n0 = blockIdx.x * 128, o0 = blockIdx.y * 128;
    const int wm0 = (wid >> 2) * 64, wn0 = (wid & 3) * 32;

    float acc[4][4][4];
#pragma unroll
    for (int i = 0; i < 4; i++)
#pragma unroll
        for (int j = 0; j < 4; j++)
#pragma unroll
            for (int e = 0; e < 4; e++) acc[i][j][e] = 0.f;

    const size_t brow = (size_t)(b * NTOK + n0) * CDIM;
    hmma_mainloop(acc, g_owh + (size_t)o0 * CDIM, g_owl + (size_t)o0 * CDIM,
                  g_th + brow, g_tl + brow,
                  smp, wm0, wn0, lane);

    const int r = lane >> 2, c2 = (lane & 3) * 2;
#pragma unroll
    for (int mi = 0; mi < 4; mi++)
#pragma unroll
        for (int ni = 0; ni < 4; ni++) {
            int o = o0 + wm0 + mi * 16 + r;
            int n = n0 + wn0 + ni * 8 + c2;
            float b0 = out_b[o], b1 = out_b[o + 8];
            float* p = out + ((size_t)(b * CDIM) + o) * NTOK + n;
            *(float2*)p = make_float2(acc[mi][ni][0] + b0, acc[mi][ni][1] + b0);
            *(float2*)(p + 8 * NTOK) =
                make_float2(acc[mi][ni][2] + b1, acc[mi][ni][3] + b1);
        }
}

// ---------------------------------------------------------------------------
// Middle kernels (unchanged)
// ---------------------------------------------------------------------------
__global__ __launch_bounds__(256) void norm_kernel()
{
    const int bh = blockIdx.x;
    const int tid = threadIdx.x;
    const int d = tid & 63, g = tid >> 6;
    const int b = bh / NHEAD, h = bh % NHEAD;
    const float* base = g_w + (size_t)b * NTOK * CDIM + h * HDIM + d;
    float acc = 0.f;
    for (int n = g; n < NTOK; n += 4) {
        float v = base[(size_t)n * CDIM];
        acc += v * v;
    }
    __shared__ float red[256];
    red[tid] = acc;
    __syncthreads();
    if (g == 0) {
        float s = red[d] + red[d + 64] + red[d + 128] + red[d + 192];
        g_ninv[bh * HDIM + d] = 1.0f / fmaxf(s, 1e-24f);
    }
}

__global__ __launch_bounds__(256) void pi_kernel(const float* __restrict__ temp)
{
    const int t = blockIdx.x * 256 + threadIdx.x;
    const int b = t >> 10, n = t & 1023;
    const float4* wrow = (const float4*)(g_w + ((size_t)b * NTOK + n) * CDIM);
    const float4* nv = (const float4*)(g_ninv + b * CDIM);

    float sv[NHEAD];
    float m = -1e30f;
#pragma unroll
    for (int h = 0; h < NHEAD; h++) {
        float a = 0.f;
#pragma unroll 4
        for (int q = 0; q < 16; q++) {
            float4 v = wrow[h * 16 + q];
            float4 u = nv[h * 16 + q];
            a += v.x * v.x * u.x + v.y * v.y * u.y + v.z * v.z * u.z + v.w * v.w * u.w;
        }
        sv[h] = a * temp[h];
        m = fmaxf(m, sv[h]);
    }
    float e[NHEAD];
    float sum = 0.f;
#pragma unroll
    for (int h = 0; h < NHEAD; h++) { e[h] = expf(sv[h] - m); sum += e[h]; }
    float inv = 1.0f / sum;
#pragma unroll
    for (int h = 0; h < NHEAD; h++)
        g_pi[((b * NHEAD + h) << 10) + n] = e[h] * inv;
}

__global__ __launch_bounds__(256) void attn_kernel()
{
    const int bh = blockIdx.x;
    const int tid = threadIdx.x;
    const int b = bh / NHEAD, h = bh % NHEAD;
    const float* pi = g_pi + bh * NTOK;

    __shared__ float red[256];
    float pp = 0.f;
    for (int n = tid; n < NTOK; n += 256) pp += pi[n];
    red[tid] = pp;
    __syncthreads();
    for (int s = 128; s > 0; s >>= 1) {
        if (tid < s) red[tid] += red[tid + s];
        __syncthreads();
    }
    float inv = 1.0f / (red[0] + 1e-8f);
    __syncthreads();

    const int d = tid & 63, g = tid >> 6;
    const float* base = g_w + (size_t)b * NTOK * CDIM + h * HDIM + d;
    float acc = 0.f;
    for (int n = g; n < NTOK; n += 4) {
        float v = base[(size_t)n * CDIM];
        acc += pi[n] * v * v;
    }
    red[tid] = acc;
    __syncthreads();
    if (g == 0) {
        float dots = (red[d] + red[d + 64] + red[d + 128] + red[d + 192]) * inv;
        g_attn[bh * HDIM + d] = 1.0f / (1.0f + dots);
    }
}

// ---------------------------------------------------------------------------
extern "C" void kernel_launch(void* const* d_in, const int* in_sizes, int n_in,
                              void* d_out, int out_size)
{
    const float* x     = (const float*)d_in[0];
    const float* qkv_w = (const float*)d_in[1];
    const float* temp  = (const float*)d_in[2];
    const float* out_w = (const float*)d_in[3];
    const float* out_b = (const float*)d_in[4];
    float* out = (float*)d_out;

    cudaFuncSetAttribute(gemm1_hmma, cudaFuncAttributeMaxDynamicSharedMemorySize, SMEM_DYN);
    cudaFuncSetAttribute(gemm2_hmma, cudaFuncAttributeMaxDynamicSharedMemorySize, SMEM_DYN);

    split_x_kernel<<<dim3(NTOK / 32, CDIM / 32, BATCH), 256>>>(x);
    split_w_kernel<<<(CDIM * CDIM / 4) / 256, 256>>>(qkv_w, 0);
    split_w_kernel<<<(CDIM * CDIM / 4) / 256, 256>>>(out_w, 1);

    dim3 g(NTOK / 128, CDIM / 128, BATCH);   // 8 x 6 x 32
    gemm1_hmma<<<g, 256, SMEM_DYN>>>();

    norm_kernel<<<BATCH * NHEAD, 256>>>();
    pi_kernel<<<(BATCH * NTOK) / 256, 256>>>(temp);
    attn_kernel<<<BATCH * NHEAD, 256>>>();

    split_t_kernel<<<(BATCH * NTOK * (CDIM / 4)) / 256, 256>>>();

    gemm2_hmma<<<g, 256, SMEM_DYN>>>(out_b, out);
}

// round 12
// speedup vs baseline: 2.1471x; 1.2761x over previous
#include <cuda_runtime.h>
#include <cuda_fp16.h>
#include <cstdint>

#define BATCH 32
#define CDIM  768
#define NTOK  1024
#define NHEAD 12
#define HDIM  64

#define KS     16                 // K per stage
#define NSTAGE (CDIM / KS)        // 48
#define NBUF   4
#define PITCHE 24                 // fp16 elems per smem row (16 data + 8 pad)
#define ASZ    (128 * PITCHE * 2) // bytes per tile array (6144)
#define BUFB   (3 * ASZ)          // bytes per stage buffer (18432): Ah, Al, B
#define SMEM_DYN (NBUF * BUFB)    // 73728

// ---------------------------------------------------------------------------
// Global scratch (no allocations allowed)
// ---------------------------------------------------------------------------
__device__ float g_w[(size_t)BATCH * NTOK * CDIM];      // W[b,n,c] fp32
__device__ float g_ninv[BATCH * NHEAD * HDIM];
__device__ float g_pi[BATCH * NHEAD * NTOK];
__device__ float g_attn[BATCH * NHEAD * HDIM];
__device__ __half g_xh[(size_t)BATCH * NTOK * CDIM];    // x^T split hi
__device__ __half g_xl[(size_t)BATCH * NTOK * CDIM];    // x^T split lo
__device__ __half g_t[(size_t)BATCH * NTOK * CDIM];     // t single fp16
__device__ __half g_qw[CDIM * CDIM];                    // qkv_w single fp16
__device__ __half g_owh[CDIM * CDIM], g_owl[CDIM * CDIM]; // out_w split

// ---------------------------------------------------------------------------
// helpers
// ---------------------------------------------------------------------------
__device__ __forceinline__ uint32_t smem_u32(const void* p) {
    return (uint32_t)__cvta_generic_to_shared(p);
}
__device__ __forceinline__ void ldmatrix_x4(unsigned& r0, unsigned& r1,
                                            unsigned& r2, unsigned& r3, uint32_t a) {
    asm volatile("ldmatrix.sync.aligned.m8n8.x4.shared.b16 {%0,%1,%2,%3}, [%4];"
                 : "=r"(r0), "=r"(r1), "=r"(r2), "=r"(r3) : "r"(a));
}
__device__ __forceinline__ void ldmatrix_x2(unsigned& r0, unsigned& r1, uint32_t a) {
    asm volatile("ldmatrix.sync.aligned.m8n8.x2.shared.b16 {%0,%1}, [%2];"
                 : "=r"(r0), "=r"(r1) : "r"(a));
}
__device__ __forceinline__ void mma16816(float* c, const unsigned* a, const unsigned* b) {
    asm volatile(
        "mma.sync.aligned.m16n8k16.row.col.f32.f16.f16.f32 "
        "{%0,%1,%2,%3}, {%4,%5,%6,%7}, {%8,%9}, {%0,%1,%2,%3};"
        : "+f"(c[0]), "+f"(c[1]), "+f"(c[2]), "+f"(c[3])
        : "r"(a[0]), "r"(a[1]), "r"(a[2]), "r"(a[3]), "r"(b[0]), "r"(b[1]));
}
#define CP16(dst, src) \
    asm volatile("cp.async.cg.shared.global [%0], [%1], 16;" \
                 :: "r"(dst), "l"(src) : "memory")
#define CP_COMMIT() asm volatile("cp.async.commit_group;" ::: "memory")
#define CP_WAIT(n)  asm volatile("cp.async.wait_group %0;" :: "n"(n) : "memory")

__device__ __forceinline__ void split1h(float v, __half& h, __half& l) {
    h = __float2half_rn(v);
    l = __float2half_rn(v - __half2float(h));
}

// ---------------------------------------------------------------------------
// Split kernels
// ---------------------------------------------------------------------------
// x[b,c,n] fp32 -> g_xh/g_xl[b,n,c] fp16 hi/lo (transpose fused)
__global__ __launch_bounds__(256) void split_x_kernel(const float* __restrict__ x)
{
    __shared__ float sm[32][33];
    const int b = blockIdx.z, c0 = blockIdx.y * 32, n0 = blockIdx.x * 32;
    const int tj = threadIdx.x & 31, ti = threadIdx.x >> 5;   // ti: 0..7
    const float* xp = x + ((size_t)b * CDIM + c0 + ti) * NTOK + n0 + tj;
#pragma unroll
    for (int k = 0; k < 4; k++)
        sm[ti + k * 8][tj] = xp[(size_t)k * 8 * NTOK];
    __syncthreads();
#pragma unroll
    for (int k = 0; k < 4; k++) {
        float v = sm[tj][ti + k * 8];
        __half h, l;
        split1h(v, h, l);
        size_t idx = ((size_t)(b * NTOK) + n0 + ti + k * 8) * CDIM + c0 + tj;
        g_xh[idx] = h;
        g_xl[idx] = l;
    }
}

// qkv_w -> single fp16 g_qw
__global__ __launch_bounds__(256) void split_qw_kernel(const float* __restrict__ w)
{
    const int t = blockIdx.x * 256 + threadIdx.x;   // 147456 float4s
    float4 v = ((const float4*)w)[t];
    __half2 a = __floats2half2_rn(v.x, v.y);
    __half2 b = __floats2half2_rn(v.z, v.w);
    *(__half2*)&g_qw[t * 4]     = a;
    *(__half2*)&g_qw[t * 4 + 2] = b;
}

// out_w -> split fp16 g_owh/g_owl
__global__ __launch_bounds__(256) void split_ow_kernel(const float* __restrict__ w)
{
    const int t = blockIdx.x * 256 + threadIdx.x;
    float4 v = ((const float4*)w)[t];
    __half h0, l0, h1, l1, h2, l2, h3, l3;
    split1h(v.x, h0, l0); split1h(v.y, h1, l1);
    split1h(v.z, h2, l2); split1h(v.w, h3, l3);
    *(__half2*)&g_owh[t * 4]     = __halves2half2(h0, h1);
    *(__half2*)&g_owh[t * 4 + 2] = __halves2half2(h2, h3);
    *(__half2*)&g_owl[t * 4]     = __halves2half2(l0, l1);
    *(__half2*)&g_owl[t * 4 + 2] = __halves2half2(l2, l3);
}

// t = -W * Pi[h,n] * attn[h,d]  -> g_t (single fp16)
__global__ __launch_bounds__(256) void split_t_kernel()
{
    const int flat = blockIdx.x * 256 + threadIdx.x;  // < 32*1024*192
    const int row = flat / 192;                       // b*1024 + n
    const int c4 = flat - row * 192;
    const int b = row >> 10, n = row & 1023;
    const int h = c4 >> 4;
    const int d = (c4 & 15) * 4;
    const float npi = -g_pi[((b * NHEAD + h) << 10) + n];
    const float4 at = *(const float4*)&g_attn[(b * NHEAD + h) * HDIM + d];
    const float4 v = *(const float4*)&g_w[(size_t)row * CDIM + c4 * 4];
    __half2 p0 = __floats2half2_rn(v.x * npi * at.x, v.y * npi * at.y);
    __half2 p1 = __floats2half2_rn(v.z * npi * at.z, v.w * npi * at.w);
    size_t idx = (size_t)row * CDIM + c4 * 4;
    *(__half2*)&g_t[idx]     = p0;
    *(__half2*)&g_t[idx + 2] = p1;
}

// ---------------------------------------------------------------------------
// HMMA mainloop: D[128x128] += (Ah+Al)[128xK] * B[128xK]^T  (fp16 2-term)
// KS=16 stages, 4 buffers, prefetch depth 3, ONE __syncthreads per stage.
// Group-count invariant: exactly one commit_group per iteration (empty at
// tail), so wait_group 2 always retires exactly stage s's data.
// (Pipeline skeleton identical to the round-9 kernel that ran clean.)
// ---------------------------------------------------------------------------
__device__ __forceinline__ void hmma_stage(
    float acc[4][4][4], uint32_t sbase, int wm0, int wn0, int lane)
{
    const int ar = wm0 + (lane & 15);
    const int ac = ((lane >> 4) & 1) * 8;
    const int br = wn0 + (lane & 7);
    const int bc = ((lane >> 3) & 1) * 8;
    const uint32_t sAh = sbase;
    const uint32_t sAl = sbase + ASZ;
    const uint32_t sB  = sbase + 2 * ASZ;

    unsigned ah[4][4], al[4][4], bf[4][2];
#pragma unroll
    for (int mi = 0; mi < 4; mi++) {
        uint32_t off = ((ar + mi * 16) * PITCHE + ac) * 2;
        ldmatrix_x4(ah[mi][0], ah[mi][1], ah[mi][2], ah[mi][3], sAh + off);
        ldmatrix_x4(al[mi][0], al[mi][1], al[mi][2], al[mi][3], sAl + off);
    }
#pragma unroll
    for (int ni = 0; ni < 4; ni++) {
        uint32_t off = ((br + ni * 8) * PITCHE + bc) * 2;
        ldmatrix_x2(bf[ni][0], bf[ni][1], sB + off);
    }
#pragma unroll
    for (int mi = 0; mi < 4; mi++)
#pragma unroll
        for (int ni = 0; ni < 4; ni++) {
            mma16816(acc[mi][ni], ah[mi], bf[ni]);
            mma16816(acc[mi][ni], al[mi], bf[ni]);
        }
}

__device__ __forceinline__ void hmma_mainloop(
    float acc[4][4][4],
    const __half* __restrict__ Ah, const __half* __restrict__ Al,
    const __half* __restrict__ B,
    char* smp, int wm0, int wn0, int lane)
{
    const int tid = threadIdx.x;
    const int row = tid >> 1;            // 0..127
    const int khe = (tid & 1) * 8;       // k elem offset (16B) within stage

    const __half* gAh = Ah + (size_t)row * CDIM + khe;
    const __half* gAl = Al + (size_t)row * CDIM + khe;
    const __half* gB  = B  + (size_t)row * CDIM + khe;
    const uint32_t sdst = smem_u32(smp) + row * (PITCHE * 2) + khe * 2;
    const uint32_t sbase0 = smem_u32(smp);

    auto issue = [&](int s) {
        const uint32_t d = sdst + (s & (NBUF - 1)) * BUFB;
        const int k0 = s * KS;
        CP16(d,           gAh + k0);
        CP16(d + ASZ,     gAl + k0);
        CP16(d + 2 * ASZ, gB + k0);
        CP_COMMIT();
    };

    issue(0);
    issue(1);
    issue(2);
#pragma unroll 1
    for (int s = 0; s < NSTAGE; s++) {
        CP_WAIT(2);            // stage s's group retired (1 commit per iteration)
        __syncthreads();       // all warps done compute(s-1) AND see stage-s data
        if (s + 3 < NSTAGE) issue(s + 3);   // writes buffer (s-1)&3 — freed by sync
        else CP_COMMIT();                    // empty group keeps count invariant
        hmma_stage(acc, sbase0 + (s & (NBUF - 1)) * BUFB, wm0, wn0, lane);
    }
}

// GEMM1: g_w[b, n, o] = sum_c x^T[n,c] * qkv_w[o,c]   (M=n, N=o)
__global__ __launch_bounds__(256, 2) void gemm1_hmma()
{
    extern __shared__ char smp[];
    const int tid = threadIdx.x, lane = tid & 31, wid = tid >> 5;
    const int b = blockIdx.z, n0 = blockIdx.x * 128, o0 = blockIdx.y * 128;
    const int wm0 = (wid >> 2) * 64, wn0 = (wid & 3) * 32;

    float acc[4][4][4];
#pragma unroll
    for (int i = 0; i < 4; i++)
#pragma unroll
        for (int j = 0; j < 4; j++)
#pragma unroll
            for (int e = 0; e < 4; e++) acc[i][j][e] = 0.f;

    const size_t arow = (size_t)(b * NTOK + n0) * CDIM;
    hmma_mainloop(acc, g_xh + arow, g_xl + arow, g_qw + (size_t)o0 * CDIM,
                  smp, wm0, wn0, lane);

    const int r = lane >> 2, c2 = (lane & 3) * 2;
#pragma unroll
    for (int mi = 0; mi < 4; mi++)
#pragma unroll
        for (int ni = 0; ni < 4; ni++) {
            int n = n0 + wm0 + mi * 16 + r;
            int o = o0 + wn0 + ni * 8 + c2;
            float* p = g_w + ((size_t)(b * NTOK) + n) * CDIM + o;
            *(float2*)p = make_float2(acc[mi][ni][0], acc[mi][ni][1]);
            *(float2*)(p + 8 * CDIM) = make_float2(acc[mi][ni][2], acc[mi][ni][3]);
        }
}

// GEMM2: out[b, o, n] = sum_c out_w[o,c] * t[n,c] + out_b[o]   (M=o, N=n)
__global__ __launch_bounds__(256, 2) void gemm2_hmma(
    const float* __restrict__ out_b, float* __restrict__ out)
{
    extern __shared__ char smp[];
    const int tid = threadIdx.x, lane = tid & 31, wid = tid >> 5;
    const int b = blockIdx.z, n0 = blockIdx.x * 128, o0 = blockIdx.y * 128;
    const int wm0 = (wid >> 2) * 64, wn0 = (wid & 3) * 32;

    float acc[4][4][4];
#pragma unroll
    for (int i = 0; i < 4; i++)
#pragma unroll
        for (int j = 0; j < 4; j++)
#pragma unroll
            for (int e = 0; e < 4; e++) acc[i][j][e] = 0.f;

    const size_t brow = (size_t)(b * NTOK + n0) * CDIM;
    hmma_mainloop(acc, g_owh + (size_t)o0 * CDIM, g_owl + (size_t)o0 * CDIM,
                  g_t + brow, smp, wm0, wn0, lane);

    const int r = lane >> 2, c2 = (lane & 3) * 2;
#pragma unroll
    for (int mi = 0; mi < 4; mi++)
#pragma unroll
        for (int ni = 0; ni < 4; ni++) {
            int o = o0 + wm0 + mi * 16 + r;
            int n = n0 + wn0 + ni * 8 + c2;
            float b0 = out_b[o], b1 = out_b[o + 8];
            float* p = out + ((size_t)(b * CDIM) + o) * NTOK + n;
            *(float2*)p = make_float2(acc[mi][ni][0] + b0, acc[mi][ni][1] + b0);
            *(float2*)(p + 8 * NTOK) =
                make_float2(acc[mi][ni][2] + b1, acc[mi][ni][3] + b1);
        }
}

// ---------------------------------------------------------------------------
// Middle kernels (unchanged)
// ---------------------------------------------------------------------------
__global__ __launch_bounds__(256) void norm_kernel()
{
    const int bh = blockIdx.x;
    const int tid = threadIdx.x;
    const int d = tid & 63, g = tid >> 6;
    const int b = bh / NHEAD, h = bh % NHEAD;
    const float* base = g_w + (size_t)b * NTOK * CDIM + h * HDIM + d;
    float acc = 0.f;
    for (int n = g; n < NTOK; n += 4) {
        float v = base[(size_t)n * CDIM];
        acc += v * v;
    }
    __shared__ float red[256];
    red[tid] = acc;
    __syncthreads();
    if (g == 0) {
        float s = red[d] + red[d + 64] + red[d + 128] + red[d + 192];
        g_ninv[bh * HDIM + d] = 1.0f / fmaxf(s, 1e-24f);
    }
}

__global__ __launch_bounds__(256) void pi_kernel(const float* __restrict__ temp)
{
    const int t = blockIdx.x * 256 + threadIdx.x;
    const int b = t >> 10, n = t & 1023;
    const float4* wrow = (const float4*)(g_w + ((size_t)b * NTOK + n) * CDIM);
    const float4* nv = (const float4*)(g_ninv + b * CDIM);

    float sv[NHEAD];
    float m = -1e30f;
#pragma unroll
    for (int h = 0; h < NHEAD; h++) {
        float a = 0.f;
#pragma unroll 4
        for (int q = 0; q < 16; q++) {
            float4 v = wrow[h * 16 + q];
            float4 u = nv[h * 16 + q];
            a += v.x * v.x * u.x + v.y * v.y * u.y + v.z * v.z * u.z + v.w * v.w * u.w;
        }
        sv[h] = a * temp[h];
        m = fmaxf(m, sv[h]);
    }
    float e[NHEAD];
    float sum = 0.f;
#pragma unroll
    for (int h = 0; h < NHEAD; h++) { e[h] = expf(sv[h] - m); sum += e[h]; }
    float inv = 1.0f / sum;
#pragma unroll
    for (int h = 0; h < NHEAD; h++)
        g_pi[((b * NHEAD + h) << 10) + n] = e[h] * inv;
}

__global__ __launch_bounds__(256) void attn_kernel()
{
    const int bh = blockIdx.x;
    const int tid = threadIdx.x;
    const int b = bh / NHEAD, h = bh % NHEAD;
    const float* pi = g_pi + bh * NTOK;

    __shared__ float red[256];
    float pp = 0.f;
    for (int n = tid; n < NTOK; n += 256) pp += pi[n];
    red[tid] = pp;
    __syncthreads();
    for (int s = 128; s > 0; s >>= 1) {
        if (tid < s) red[tid] += red[tid + s];
        __syncthreads();
    }
    float inv = 1.0f / (red[0] + 1e-8f);
    __syncthreads();

    const int d = tid & 63, g = tid >> 6;
    const float* base = g_w + (size_t)b * NTOK * CDIM + h * HDIM + d;
    float acc = 0.f;
    for (int n = g; n < NTOK; n += 4) {
        float v = base[(size_t)n * CDIM];
        acc += pi[n] * v * v;
    }
    red[tid] = acc;
    __syncthreads();
    if (g == 0) {
        float dots = (red[d] + red[d + 64] + red[d + 128] + red[d + 192]) * inv;
        g_attn[bh * HDIM + d] = 1.0f / (1.0f + dots);
    }
}

// ---------------------------------------------------------------------------
extern "C" void kernel_launch(void* const* d_in, const int* in_sizes, int n_in,
                              void* d_out, int out_size)
{
    const float* x     = (const float*)d_in[0];
    const float* qkv_w = (const float*)d_in[1];
    const float* temp  = (const float*)d_in[2];
    const float* out_w = (const float*)d_in[3];
    const float* out_b = (const float*)d_in[4];
    float* out = (float*)d_out;

    cudaFuncSetAttribute(gemm1_hmma, cudaFuncAttributeMaxDynamicSharedMemorySize, SMEM_DYN);
    cudaFuncSetAttribute(gemm2_hmma, cudaFuncAttributeMaxDynamicSharedMemorySize, SMEM_DYN);

    split_x_kernel<<<dim3(NTOK / 32, CDIM / 32, BATCH), 256>>>(x);
    split_qw_kernel<<<(CDIM * CDIM / 4) / 256, 256>>>(qkv_w);
    split_ow_kernel<<<(CDIM * CDIM / 4) / 256, 256>>>(out_w);

    dim3 g(NTOK / 128, CDIM / 128, BATCH);   // 8 x 6 x 32
    gemm1_hmma<<<g, 256, SMEM_DYN>>>();

    norm_kernel<<<BATCH * NHEAD, 256>>>();
    pi_kernel<<<(BATCH * NTOK) / 256, 256>>>(temp);
    attn_kernel<<<BATCH * NHEAD, 256>>>();

    split_t_kernel<<<(BATCH * NTOK * (CDIM / 4)) / 256, 256>>>();

    gemm2_hmma<<<g, 256, SMEM_DYN>>>(out_b, out);
}

// round 13
// speedup vs baseline: 2.1589x; 1.0055x over previous
#include <cuda_runtime.h>
#include <cuda_fp16.h>
#include <cstdint>

#define BATCH 32
#define CDIM  768
#define NTOK  1024
#define NHEAD 12
#define HDIM  64

#define KS     16                 // K per stage
#define NSTAGE (CDIM / KS)        // 48
#define NBUF   4
#define PITCHE 24                 // fp16 elems per smem row (16 data + 8 pad)
#define ASZ    (128 * PITCHE * 2) // bytes per tile array (6144)
#define BUFB   (3 * ASZ)          // bytes per stage buffer (18432): Ah, Al, B
#define SMEM_DYN (NBUF * BUFB)    // 73728

// ---------------------------------------------------------------------------
// Global scratch (no allocations allowed)
// ---------------------------------------------------------------------------
__device__ float g_w[(size_t)BATCH * NTOK * CDIM];      // W[b,n,c] fp32
__device__ float g_ninv[BATCH * NHEAD * HDIM];
__device__ float g_pi[BATCH * NHEAD * NTOK];
__device__ float g_attn[BATCH * NHEAD * HDIM];
__device__ __half g_xh[(size_t)BATCH * NTOK * CDIM];    // x^T split hi
__device__ __half g_xl[(size_t)BATCH * NTOK * CDIM];    // x^T split lo
__device__ __half g_t[(size_t)BATCH * NTOK * CDIM];     // t single fp16
__device__ __half g_qw[CDIM * CDIM];                    // qkv_w single fp16
__device__ __half g_owh[CDIM * CDIM], g_owl[CDIM * CDIM]; // out_w split

// ---------------------------------------------------------------------------
// helpers
// ---------------------------------------------------------------------------
__device__ __forceinline__ uint32_t smem_u32(const void* p) {
    return (uint32_t)__cvta_generic_to_shared(p);
}
__device__ __forceinline__ void ldmatrix_x4(unsigned& r0, unsigned& r1,
                                            unsigned& r2, unsigned& r3, uint32_t a) {
    asm volatile("ldmatrix.sync.aligned.m8n8.x4.shared.b16 {%0,%1,%2,%3}, [%4];"
                 : "=r"(r0), "=r"(r1), "=r"(r2), "=r"(r3) : "r"(a));
}
__device__ __forceinline__ void ldmatrix_x2(unsigned& r0, unsigned& r1, uint32_t a) {
    asm volatile("ldmatrix.sync.aligned.m8n8.x2.shared.b16 {%0,%1}, [%2];"
                 : "=r"(r0), "=r"(r1) : "r"(a));
}
__device__ __forceinline__ void mma16816(float* c, const unsigned* a, const unsigned* b) {
    asm volatile(
        "mma.sync.aligned.m16n8k16.row.col.f32.f16.f16.f32 "
        "{%0,%1,%2,%3}, {%4,%5,%6,%7}, {%8,%9}, {%0,%1,%2,%3};"
        : "+f"(c[0]), "+f"(c[1]), "+f"(c[2]), "+f"(c[3])
        : "r"(a[0]), "r"(a[1]), "r"(a[2]), "r"(a[3]), "r"(b[0]), "r"(b[1]));
}
#define CP16(dst, src) \
    asm volatile("cp.async.cg.shared.global [%0], [%1], 16;" \
                 :: "r"(dst), "l"(src) : "memory")
#define CP_COMMIT() asm volatile("cp.async.commit_group;" ::: "memory")
#define CP_WAIT(n)  asm volatile("cp.async.wait_group %0;" :: "n"(n) : "memory")

__device__ __forceinline__ void split1h(float v, __half& h, __half& l) {
    h = __float2half_rn(v);
    l = __float2half_rn(v - __half2float(h));
}

// ---------------------------------------------------------------------------
// Split kernels
// ---------------------------------------------------------------------------
// x[b,c,n] fp32 -> g_xh/g_xl[b,n,c] fp16 hi/lo (transpose fused)
__global__ __launch_bounds__(256) void split_x_kernel(const float* __restrict__ x)
{
    __shared__ float sm[32][33];
    const int b = blockIdx.z, c0 = blockIdx.y * 32, n0 = blockIdx.x * 32;
    const int tj = threadIdx.x & 31, ti = threadIdx.x >> 5;   // ti: 0..7
    const float* xp = x + ((size_t)b * CDIM + c0 + ti) * NTOK + n0 + tj;
#pragma unroll
    for (int k = 0; k < 4; k++)
        sm[ti + k * 8][tj] = xp[(size_t)k * 8 * NTOK];
    __syncthreads();
#pragma unroll
    for (int k = 0; k < 4; k++) {
        float v = sm[tj][ti + k * 8];
        __half h, l;
        split1h(v, h, l);
        size_t idx = ((size_t)(b * NTOK) + n0 + ti + k * 8) * CDIM + c0 + tj;
        g_xh[idx] = h;
        g_xl[idx] = l;
    }
}

// qkv_w -> single fp16 g_qw
__global__ __launch_bounds__(256) void split_qw_kernel(const float* __restrict__ w)
{
    const int t = blockIdx.x * 256 + threadIdx.x;   // 147456 float4s
    float4 v = ((const float4*)w)[t];
    __half2 a = __floats2half2_rn(v.x, v.y);
    __half2 b = __floats2half2_rn(v.z, v.w);
    *(__half2*)&g_qw[t * 4]     = a;
    *(__half2*)&g_qw[t * 4 + 2] = b;
}

// out_w -> split fp16 g_owh/g_owl
__global__ __launch_bounds__(256) void split_ow_kernel(const float* __restrict__ w)
{
    const int t = blockIdx.x * 256 + threadIdx.x;
    float4 v = ((const float4*)w)[t];
    __half h0, l0, h1, l1, h2, l2, h3, l3;
    split1h(v.x, h0, l0); split1h(v.y, h1, l1);
    split1h(v.z, h2, l2); split1h(v.w, h3, l3);
    *(__half2*)&g_owh[t * 4]     = __halves2half2(h0, h1);
    *(__half2*)&g_owh[t * 4 + 2] = __halves2half2(h2, h3);
    *(__half2*)&g_owl[t * 4]     = __halves2half2(l0, l1);
    *(__half2*)&g_owl[t * 4 + 2] = __halves2half2(l2, l3);
}

// t = -W * Pi[h,n] * attn[h,d]  -> g_t (single fp16)
__global__ __launch_bounds__(256) void split_t_kernel()
{
    const int flat = blockIdx.x * 256 + threadIdx.x;  // < 32*1024*192
    const int row = flat / 192;                       // b*1024 + n
    const int c4 = flat - row * 192;
    const int b = row >> 10, n = row & 1023;
    const int h = c4 >> 4;
    const int d = (c4 & 15) * 4;
    const float npi = -g_pi[((b * NHEAD + h) << 10) + n];
    const float4 at = *(const float4*)&g_attn[(b * NHEAD + h) * HDIM + d];
    const float4 v = *(const float4*)&g_w[(size_t)row * CDIM + c4 * 4];
    __half2 p0 = __floats2half2_rn(v.x * npi * at.x, v.y * npi * at.y);
    __half2 p1 = __floats2half2_rn(v.z * npi * at.z, v.w * npi * at.w);
    size_t idx = (size_t)row * CDIM + c4 * 4;
    *(__half2*)&g_t[idx]     = p0;
    *(__half2*)&g_t[idx + 2] = p1;
}

// ---------------------------------------------------------------------------
// HMMA mainloop: D[128x128] += (Ah+Al)[128xK] * B[128xK]^T  (fp16 2-term)
// KS=16 stages, 4 buffers, prefetch depth 3, one __syncthreads per stage.
// Stage compute is software-pipelined at mi granularity (2-slot register
// buffer for A fragments): ldmatrix for mi+1 issues before the mma block of
// mi, so LDSM latency/throughput overlaps tensor work instead of phasing
// with it. No intra-stage sync -> warps also drift out of phase, overlapping
// smem and tensor pipes across warps.
// ---------------------------------------------------------------------------
__device__ __forceinline__ void hmma_stage(
    float acc[4][4][4], uint32_t sbase, int wm0, int wn0, int lane)
{
    const int ar = wm0 + (lane & 15);
    const int ac = ((lane >> 4) & 1) * 8;
    const int br = wn0 + (lane & 7);
    const int bc = ((lane >> 3) & 1) * 8;
    const uint32_t sAh = sbase;
    const uint32_t sAl = sbase + ASZ;
    const uint32_t sB  = sbase + 2 * ASZ;

    unsigned bf[4][2];
#pragma unroll
    for (int ni = 0; ni < 4; ni++) {
        uint32_t off = ((br + ni * 8) * PITCHE + bc) * 2;
        ldmatrix_x2(bf[ni][0], bf[ni][1], sB + off);
    }

    unsigned ah[2][4], al[2][4];   // 2-slot pipeline for A fragments
    {
        uint32_t off = (ar * PITCHE + ac) * 2;
        ldmatrix_x4(ah[0][0], ah[0][1], ah[0][2], ah[0][3], sAh + off);
        ldmatrix_x4(al[0][0], al[0][1], al[0][2], al[0][3], sAl + off);
    }
#pragma unroll
    for (int mi = 0; mi < 4; mi++) {
        const int cur = mi & 1, nxt = cur ^ 1;
        if (mi < 3) {
            uint32_t off = ((ar + (mi + 1) * 16) * PITCHE + ac) * 2;
            ldmatrix_x4(ah[nxt][0], ah[nxt][1], ah[nxt][2], ah[nxt][3], sAh + off);
            ldmatrix_x4(al[nxt][0], al[nxt][1], al[nxt][2], al[nxt][3], sAl + off);
        }
#pragma unroll
        for (int ni = 0; ni < 4; ni++) {
            mma16816(acc[mi][ni], ah[cur], bf[ni]);
            mma16816(acc[mi][ni], al[cur], bf[ni]);
        }
    }
}

__device__ __forceinline__ void hmma_mainloop(
    float acc[4][4][4],
    const __half* __restrict__ Ah, const __half* __restrict__ Al,
    const __half* __restrict__ B,
    char* smp, int wm0, int wn0, int lane)
{
    const int tid = threadIdx.x;
    const int row = tid >> 1;            // 0..127
    const int khe = (tid & 1) * 8;       // k elem offset (16B) within stage

    const __half* gAh = Ah + (size_t)row * CDIM + khe;
    const __half* gAl = Al + (size_t)row * CDIM + khe;
    const __half* gB  = B  + (size_t)row * CDIM + khe;
    const uint32_t sdst = smem_u32(smp) + row * (PITCHE * 2) + khe * 2;
    const uint32_t sbase0 = smem_u32(smp);

    auto issue = [&](int s) {
        const uint32_t d = sdst + (s & (NBUF - 1)) * BUFB;
        const int k0 = s * KS;
        CP16(d,           gAh + k0);
        CP16(d + ASZ,     gAl + k0);
        CP16(d + 2 * ASZ, gB + k0);
        CP_COMMIT();
    };

    issue(0);
    issue(1);
    issue(2);
#pragma unroll 1
    for (int s = 0; s < NSTAGE; s++) {
        CP_WAIT(2);            // stage s's group retired (1 commit per iteration)
        __syncthreads();       // all warps done compute(s-1) AND see stage-s data
        if (s + 3 < NSTAGE) issue(s + 3);   // writes buffer (s-1)&3 — freed by sync
        else CP_COMMIT();                    // empty group keeps count invariant
        hmma_stage(acc, sbase0 + (s & (NBUF - 1)) * BUFB, wm0, wn0, lane);
    }
}

// GEMM1: g_w[b, n, o] = sum_c x^T[n,c] * qkv_w[o,c]   (M=n, N=o)
__global__ __launch_bounds__(256, 2) void gemm1_hmma()
{
    extern __shared__ char smp[];
    const int tid = threadIdx.x, lane = tid & 31, wid = tid >> 5;
    const int b = blockIdx.z, n0 = blockIdx.x * 128, o0 = blockIdx.y * 128;
    const int wm0 = (wid >> 2) * 64, wn0 = (wid & 3) * 32;

    float acc[4][4][4];
#pragma unroll
    for (int i = 0; i < 4; i++)
#pragma unroll
        for (int j = 0; j < 4; j++)
#pragma unroll
            for (int e = 0; e < 4; e++) acc[i][j][e] = 0.f;

    const size_t arow = (size_t)(b * NTOK + n0) * CDIM;
    hmma_mainloop(acc, g_xh + arow, g_xl + arow, g_qw + (size_t)o0 * CDIM,
                  smp, wm0, wn0, lane);

    const int r = lane >> 2, c2 = (lane & 3) * 2;
#pragma unroll
    for (int mi = 0; mi < 4; mi++)
#pragma unroll
        for (int ni = 0; ni < 4; ni++) {
            int n = n0 + wm0 + mi * 16 + r;
            int o = o0 + wn0 + ni * 8 + c2;
            float* p = g_w + ((size_t)(b * NTOK) + n) * CDIM + o;
            *(float2*)p = make_float2(acc[mi][ni][0], acc[mi][ni][1]);
            *(float2*)(p + 8 * CDIM) = make_float2(acc[mi][ni][2], acc[mi][ni][3]);
        }
}

// GEMM2: out[b, o, n] = sum_c out_w[o,c] * t[n,c] + out_b[o]   (M=o, N=n)
__global__ __launch_bounds__(256, 2) void gemm2_hmma(
    const float* __restrict__ out_b, float* __restrict__ out)
{
    extern __shared__ char smp[];
    const int tid = threadIdx.x, lane = tid & 31, wid = tid >> 5;
    const int b = blockIdx.z, n0 = blockIdx.x * 128, o0 = blockIdx.y * 128;
    const int wm0 = (wid >> 2) * 64, wn0 = (wid & 3) * 32;

    float acc[4][4][4];
#pragma unroll
    for (int i = 0; i < 4; i++)
#pragma unroll
        for (int j = 0; j < 4; j++)
#pragma unroll
            for (int e = 0; e < 4; e++) acc[i][j][e] = 0.f;

    const size_t brow = (size_t)(b * NTOK + n0) * CDIM;
    hmma_mainloop(acc, g_owh + (size_t)o0 * CDIM, g_owl + (size_t)o0 * CDIM,
                  g_t + brow, smp, wm0, wn0, lane);

    const int r = lane >> 2, c2 = (lane & 3) * 2;
#pragma unroll
    for (int mi = 0; mi < 4; mi++)
#pragma unroll
        for (int ni = 0; ni < 4; ni++) {
            int o = o0 + wm0 + mi * 16 + r;
            int n = n0 + wn0 + ni * 8 + c2;
            float b0 = out_b[o], b1 = out_b[o + 8];
            float* p = out + ((size_t)(b * CDIM) + o) * NTOK + n;
            *(float2*)p = make_float2(acc[mi][ni][0] + b0, acc[mi][ni][1] + b0);
            *(float2*)(p + 8 * NTOK) =
                make_float2(acc[mi][ni][2] + b1, acc[mi][ni][3] + b1);
        }
}

// ---------------------------------------------------------------------------
// Middle kernels (unchanged)
// ---------------------------------------------------------------------------
__global__ __launch_bounds__(256) void norm_kernel()
{
    const int bh = blockIdx.x;
    const int tid = threadIdx.x;
    const int d = tid & 63, g = tid >> 6;
    const int b = bh / NHEAD, h = bh % NHEAD;
    const float* base = g_w + (size_t)b * NTOK * CDIM + h * HDIM + d;
    float acc = 0.f;
    for (int n = g; n < NTOK; n += 4) {
        float v = base[(size_t)n * CDIM];
        acc += v * v;
    }
    __shared__ float red[256];
    red[tid] = acc;
    __syncthreads();
    if (g == 0) {
        float s = red[d] + red[d + 64] + red[d + 128] + red[d + 192];
        g_ninv[bh * HDIM + d] = 1.0f / fmaxf(s, 1e-24f);
    }
}

__global__ __launch_bounds__(256) void pi_kernel(const float* __restrict__ temp)
{
    const int t = blockIdx.x * 256 + threadIdx.x;
    const int b = t >> 10, n = t & 1023;
    const float4* wrow = (const float4*)(g_w + ((size_t)b * NTOK + n) * CDIM);
    const float4* nv = (const float4*)(g_ninv + b * CDIM);

    float sv[NHEAD];
    float m = -1e30f;
#pragma unroll
    for (int h = 0; h < NHEAD; h++) {
        float a = 0.f;
#pragma unroll 4
        for (int q = 0; q < 16; q++) {
            float4 v = wrow[h * 16 + q];
            float4 u = nv[h * 16 + q];
            a += v.x * v.x * u.x + v.y * v.y * u.y + v.z * v.z * u.z + v.w * v.w * u.w;
        }
        sv[h] = a * temp[h];
        m = fmaxf(m, sv[h]);
    }
    float e[NHEAD];
    float sum = 0.f;
#pragma unroll
    for (int h = 0; h < NHEAD; h++) { e[h] = expf(sv[h] - m); sum += e[h]; }
    float inv = 1.0f / sum;
#pragma unroll
    for (int h = 0; h < NHEAD; h++)
        g_pi[((b * NHEAD + h) << 10) + n] = e[h] * inv;
}

__global__ __launch_bounds__(256) void attn_kernel()
{
    const int bh = blockIdx.x;
    const int tid = threadIdx.x;
    const int b = bh / NHEAD, h = bh % NHEAD;
    const float* pi = g_pi + bh * NTOK;

    __shared__ float red[256];
    float pp = 0.f;
    for (int n = tid; n < NTOK; n += 256) pp += pi[n];
    red[tid] = pp;
    __syncthreads();
    for (int s = 128; s > 0; s >>= 1) {
        if (tid < s) red[tid] += red[tid + s];
        __syncthreads();
    }
    float inv = 1.0f / (red[0] + 1e-8f);
    __syncthreads();

    const int d = tid & 63, g = tid >> 6;
    const float* base = g_w + (size_t)b * NTOK * CDIM + h * HDIM + d;
    float acc = 0.f;
    for (int n = g; n < NTOK; n += 4) {
        float v = base[(size_t)n * CDIM];
        acc += pi[n] * v * v;
    }
    red[tid] = acc;
    __syncthreads();
    if (g == 0) {
        float dots = (red[d] + red[d + 64] + red[d + 128] + red[d + 192]) * inv;
        g_attn[bh * HDIM + d] = 1.0f / (1.0f + dots);
    }
}

// ---------------------------------------------------------------------------
extern "C" void kernel_launch(void* const* d_in, const int* in_sizes, int n_in,
                              void* d_out, int out_size)
{
    const float* x     = (const float*)d_in[0];
    const float* qkv_w = (const float*)d_in[1];
    const float* temp  = (const float*)d_in[2];
    const float* out_w = (const float*)d_in[3];
    const float* out_b = (const float*)d_in[4];
    float* out = (float*)d_out;

    cudaFuncSetAttribute(gemm1_hmma, cudaFuncAttributeMaxDynamicSharedMemorySize, SMEM_DYN);
    cudaFuncSetAttribute(gemm2_hmma, cudaFuncAttributeMaxDynamicSharedMemorySize, SMEM_DYN);

    split_x_kernel<<<dim3(NTOK / 32, CDIM / 32, BATCH), 256>>>(x);
    split_qw_kernel<<<(CDIM * CDIM / 4) / 256, 256>>>(qkv_w);
    split_ow_kernel<<<(CDIM * CDIM / 4) / 256, 256>>>(out_w);

    dim3 g(NTOK / 128, CDIM / 128, BATCH);   // 8 x 6 x 32
    gemm1_hmma<<<g, 256, SMEM_DYN>>>();

    norm_kernel<<<BATCH * NHEAD, 256>>>();
    pi_kernel<<<(BATCH * NTOK) / 256, 256>>>(temp);
    attn_kernel<<<BATCH * NHEAD, 256>>>();

    split_t_kernel<<<(BATCH * NTOK * (CDIM / 4)) / 256, 256>>>();

    gemm2_hmma<<<g, 256, SMEM_DYN>>>(out_b, out);
}